// round 2
// baseline (speedup 1.0000x reference)
#include <cuda_runtime.h>
#include <math.h>

#define B 4
#define S 256
#define E 256
#define H 8
#define DH 32
#define LD 128
#define NN 65536
#define NC 2
#define EPS 1e-5f

// ---------------- scratch (static device memory; no allocation) ----------------
__device__ __align__(16) float g_q[B*H*S*DH];
__device__ __align__(16) float g_k[B*H*S*DH];
__device__ __align__(16) float g_v[B*H*S*DH];
__device__ __align__(16) float g_ctx[B*S*E];
__device__ __align__(16) float g_attn[B*S*E];
__device__ int g_cid[NN];

// ---------------- kernel 1: cluster ids from np_cluster ----------------
__global__ void prep_kernel(const int* __restrict__ npc) {
    __shared__ int vals[S];
    __shared__ int pref[S + 1];
    int t = threadIdx.x;
    vals[t] = npc[t];
    __syncthreads();
    if (t == 0) {
        int a = 0;
        for (int s = 0; s < S; s++) { pref[s] = a; a += vals[s]; }
        pref[S] = a;
    }
    __syncthreads();
    int st = pref[t];
    int en = pref[t + 1];
    if (en > NN) en = NN;
    for (int i = st; i < en && i < NN; i++) g_cid[i] = t;
    if (t == 0) {
        int tail = pref[S];
        for (int i = tail; i < NN; i++) g_cid[i] = S - 1;
    }
}

// ---------------- kernel 2: x = gl^T + pos(centroids); qkv = x @ Win^T + b ----------------
// grid (S/8, B), 256 threads
__global__ void xqkv_kernel(const float* __restrict__ gl, const float* __restrict__ cent,
                            const float* __restrict__ fc1w, const float* __restrict__ fc1b,
                            const float* __restrict__ fc2w, const float* __restrict__ fc2b,
                            const float* __restrict__ inw, const float* __restrict__ inb) {
    const int t = threadIdx.x;
    const int b = blockIdx.y;
    const int s0 = blockIdx.x * 8;
    __shared__ float xs[8 * 260];
    __shared__ float wt[64 * 68];

    // per-thread channel t: precompute pos weights
    float w2r[16];
#pragma unroll
    for (int j = 0; j < 16; j++) w2r[j] = fc2w[t * 16 + j];
    float fb = fc2b[t];
    for (int sr = 0; sr < 8; sr++) {
        int s = s0 + sr;
        float c0v = cent[(b * S + s) * 2 + 0];
        float c1v = cent[(b * S + s) * 2 + 1];
        float pos = fb;
#pragma unroll
        for (int j = 0; j < 16; j++) {
            float hh = fc1b[j] + c0v * fc1w[2 * j] + c1v * fc1w[2 * j + 1];
            hh = (hh >= 0.f) ? hh : 0.01f * hh;
            pos += hh * w2r[j];
        }
        xs[sr * 260 + t] = gl[(s * B + b) * E + t] + pos;
    }

    const int ol = t >> 2, sg = t & 3;
    for (int chunk = 0; chunk < 12; chunk++) {
        float acc0 = 0.f, acc1 = 0.f;
        for (int kt = 0; kt < 256; kt += 64) {
            __syncthreads();
            for (int i = t; i < 4096; i += 256) {
                int o = i >> 6, k = i & 63;
                wt[o * 68 + k] = inw[(chunk * 64 + o) * 256 + kt + k];
            }
            __syncthreads();
#pragma unroll
            for (int kl = 0; kl < 64; kl += 4) {
                float4 wv = *(float4*)&wt[ol * 68 + kl];
                float4 a0 = *(float4*)&xs[sg * 260 + kt + kl];
                float4 a1 = *(float4*)&xs[(sg + 4) * 260 + kt + kl];
                acc0 += wv.x * a0.x + wv.y * a0.y + wv.z * a0.z + wv.w * a0.w;
                acc1 += wv.x * a1.x + wv.y * a1.y + wv.z * a1.z + wv.w * a1.w;
            }
        }
        int o = chunk * 64 + ol;
        float bb = inb[o];
        int part = o >> 8, e = o & 255, hh = e >> 5, d = e & 31;
        float* dst = (part == 0) ? g_q : ((part == 1) ? g_k : g_v);
        int sa = s0 + sg, sb = s0 + sg + 4;
        dst[((b * H + hh) * S + sa) * DH + d] = acc0 + bb;
        dst[((b * H + hh) * S + sb) * DH + d] = acc1 + bb;
    }
}

// ---------------- kernel 3: attention (online softmax), grid (S/64, H, B), 64 threads ----------------
__global__ void attn_kernel() {
    extern __shared__ float sh[];   // ks[256*32], vs[256*32]
    float* ks = sh;
    float* vs = sh + S * DH;
    const int t = threadIdx.x;
    const int b = blockIdx.z, h = blockIdx.y;
    const int base = ((b * H + h) * S) * DH;
    for (int i = t; i < S * DH / 4; i += 64) {
        ((float4*)ks)[i] = ((const float4*)(g_k + base))[i];
        ((float4*)vs)[i] = ((const float4*)(g_v + base))[i];
    }
    __syncthreads();
    const int q = blockIdx.x * 64 + t;
    float qr[DH];
#pragma unroll
    for (int i = 0; i < DH / 4; i++) ((float4*)qr)[i] = ((const float4*)(g_q + base + q * DH))[i];
    const float scale = 0.17677669529663687f;  // 1/sqrt(32)
    float m = -1e30f, l = 0.f, acc[DH];
#pragma unroll
    for (int d = 0; d < DH; d++) acc[d] = 0.f;
    for (int j = 0; j < S; j++) {
        float sc = 0.f;
#pragma unroll
        for (int d = 0; d < DH; d++) sc += qr[d] * ks[j * DH + d];
        sc *= scale;
        if (sc <= m) {
            float p = __expf(sc - m);
            l += p;
#pragma unroll
            for (int d = 0; d < DH; d++) acc[d] += p * vs[j * DH + d];
        } else {
            float corr = __expf(m - sc);
            m = sc;
            l = l * corr + 1.f;
#pragma unroll
            for (int d = 0; d < DH; d++) acc[d] = acc[d] * corr + vs[j * DH + d];
        }
    }
    float inv = 1.f / l;
#pragma unroll
    for (int d = 0; d < DH; d++) g_ctx[(b * S + q) * E + h * DH + d] = acc[d] * inv;
}

// ---------------- kernel 4: out_proj, grid (S/8, B), 256 threads ----------------
__global__ void outproj_kernel(const float* __restrict__ ow, const float* __restrict__ ob) {
    const int t = threadIdx.x;
    const int b = blockIdx.y;
    const int s0 = blockIdx.x * 8;
    __shared__ float cs[8 * 260];
    __shared__ float wt[64 * 68];
    for (int i = t; i < 8 * 256; i += 256) {
        int sr = i >> 8, e = i & 255;
        cs[sr * 260 + e] = g_ctx[(b * S + s0 + sr) * E + e];
    }
    const int ol = t >> 2, sg = t & 3;
    for (int chunk = 0; chunk < 4; chunk++) {
        float acc0 = 0.f, acc1 = 0.f;
        for (int kt = 0; kt < 256; kt += 64) {
            __syncthreads();
            for (int i = t; i < 4096; i += 256) {
                int o = i >> 6, k = i & 63;
                wt[o * 68 + k] = ow[(chunk * 64 + o) * 256 + kt + k];
            }
            __syncthreads();
#pragma unroll
            for (int kl = 0; kl < 64; kl += 4) {
                float4 wv = *(float4*)&wt[ol * 68 + kl];
                float4 a0 = *(float4*)&cs[sg * 260 + kt + kl];
                float4 a1 = *(float4*)&cs[(sg + 4) * 260 + kt + kl];
                acc0 += wv.x * a0.x + wv.y * a0.y + wv.z * a0.z + wv.w * a0.w;
                acc1 += wv.x * a1.x + wv.y * a1.y + wv.z * a1.z + wv.w * a1.w;
            }
        }
        int o = chunk * 64 + ol;
        float bb = ob[o];
        g_attn[(b * S + s0 + sg) * E + o] = acc0 + bb;
        g_attn[(b * S + s0 + sg + 4) * E + o] = acc1 + bb;
    }
}

// ---------------- kernel 5: fused point-MLP (gather + conv2/bn/relu + conv3/bn/relu + conv4 + transpose) ----------------
// grid (NN/32, B), 512 threads. lanes = points (32), warps = channel groups.
#define PCS 396   // pad: p*396/4 mod 32 is a permutation -> conflict-free LDS.128
#define H2S 140   // same property
#define H3S 65

__global__ void mlp_kernel(const float* __restrict__ lo,
                           const float* __restrict__ w2, const float* __restrict__ cb2,
                           const float* __restrict__ gm2, const float* __restrict__ bt2,
                           const float* __restrict__ mu2, const float* __restrict__ va2,
                           const float* __restrict__ w3, const float* __restrict__ cb3,
                           const float* __restrict__ gm3, const float* __restrict__ bt3,
                           const float* __restrict__ mu3, const float* __restrict__ va3,
                           const float* __restrict__ w4, const float* __restrict__ b4,
                           float* __restrict__ out) {
    extern __shared__ float sm[];
    float* pc  = sm;                // 32*396
    float* h2  = pc + 32 * PCS;     // 32*140
    float* h3  = h2 + 32 * H2S;     // 32*65
    float* wb  = h3 + 32 * H3S;     // 4096
    float* sc2 = wb + 4096;         // 128
    float* bi2 = sc2 + 128;         // 128
    float* sc3 = bi2 + 128;         // 64
    float* bi3 = sc3 + 64;          // 64
    int*   cid = (int*)(bi3 + 64);  // 32

    const int t = threadIdx.x;
    const int b = blockIdx.y;
    const int n0 = blockIdx.x * 32;

    if (t < 128) {
        float s = gm2[t] * rsqrtf(va2[t] + EPS);
        sc2[t] = s;
        bi2[t] = (cb2[t] - mu2[t]) * s + bt2[t];
    } else if (t < 192) {
        int c = t - 128;
        float s = gm3[c] * rsqrtf(va3[c] + EPS);
        sc3[c] = s;
        bi3[c] = (cb3[c] - mu3[c]) * s + bt3[c];
    } else if (t < 224) {
        cid[t - 192] = g_cid[n0 + t - 192];
    }
    __syncthreads();

    // gather pc = [lo_feats | attn_out[cid]]  (float4, boundary at col 128 is aligned)
    for (int i4 = t; i4 < 32 * 96; i4 += 512) {
        int idx = i4 * 4;
        int p = idx / 384, col = idx - p * 384;
        float4 v;
        if (col < 128) v = *(const float4*)&lo[(b * NN + n0 + p) * LD + col];
        else           v = *(const float4*)&g_attn[(b * S + cid[p]) * E + (col - 128)];
        *(float4*)&pc[p * PCS + col] = v;
    }

    const int wg = t >> 5, p = t & 31;

    // ---- stage 1: h2[p][c] = relu(pc . W2'[c] + b2')  (bn folded) ----
    {
        const int c0 = wg * 8;
        float acc[8];
#pragma unroll
        for (int j = 0; j < 8; j++) acc[j] = 0.f;
        for (int kt = 0; kt < 384; kt += 32) {
            __syncthreads();
            for (int i = t; i < 4096; i += 512) {
                int c = i >> 5, kk = i & 31;
                wb[i] = w2[c * 384 + kt + kk] * sc2[c];
            }
            __syncthreads();
#pragma unroll
            for (int kl = 0; kl < 32; kl += 4) {
                float4 av = *(float4*)&pc[p * PCS + kt + kl];
#pragma unroll
                for (int j = 0; j < 8; j++) {
                    float4 wv = *(float4*)&wb[(c0 + j) * 32 + kl];  // uniform broadcast
                    acc[j] += av.x * wv.x + av.y * wv.y + av.z * wv.z + av.w * wv.w;
                }
            }
        }
#pragma unroll
        for (int j = 0; j < 8; j++) {
            float v = acc[j] + bi2[c0 + j];
            h2[p * H2S + c0 + j] = (v > 0.f) ? v : 0.f;
        }
    }
    __syncthreads();

    // ---- stage 2: h3 = relu(h2 . W3' + b3') ----
    {
        const int c0 = wg * 4;
        float acc[4] = {0.f, 0.f, 0.f, 0.f};
        for (int kt = 0; kt < 128; kt += 32) {
            __syncthreads();
            for (int i = t; i < 2048; i += 512) {
                int c = i >> 5, kk = i & 31;
                wb[i] = w3[c * 128 + kt + kk] * sc3[c];
            }
            __syncthreads();
#pragma unroll
            for (int kl = 0; kl < 32; kl += 4) {
                float4 av = *(float4*)&h2[p * H2S + kt + kl];
#pragma unroll
                for (int j = 0; j < 4; j++) {
                    float4 wv = *(float4*)&wb[(c0 + j) * 32 + kl];
                    acc[j] += av.x * wv.x + av.y * wv.y + av.z * wv.z + av.w * wv.w;
                }
            }
        }
#pragma unroll
        for (int j = 0; j < 4; j++) {
            float v = acc[j] + bi3[c0 + j];
            h3[p * H3S + c0 + j] = (v > 0.f) ? v : 0.f;
        }
    }
    __syncthreads();

    // ---- stage 3: out[b][c][n] = h3 . W4[c] + b4[c]  (transposed write) ----
    if (t < 64) {
        int pp = t >> 1, c = t & 1;
        float a = b4[c];
#pragma unroll
        for (int k = 0; k < 64; k++) a += h3[pp * H3S + k] * __ldg(&w4[c * 64 + k]);
        out[(b * NC + c) * NN + n0 + pp] = a;
    }
}

// ---------------- launch ----------------
extern "C" void kernel_launch(void* const* d_in, const int* in_sizes, int n_in,
                              void* d_out, int out_size) {
    const float* gl    = (const float*)d_in[0];
    const float* lo    = (const float*)d_in[1];
    const float* cent  = (const float*)d_in[2];
    const int*   npc   = (const int*)  d_in[3];
    const float* fc1w  = (const float*)d_in[4];
    const float* fc1b  = (const float*)d_in[5];
    const float* fc2w  = (const float*)d_in[6];
    const float* fc2b  = (const float*)d_in[7];
    const float* inw   = (const float*)d_in[8];
    const float* inb   = (const float*)d_in[9];
    const float* ow    = (const float*)d_in[10];
    const float* ob    = (const float*)d_in[11];
    const float* w2    = (const float*)d_in[12];
    const float* cb2   = (const float*)d_in[13];
    const float* gm2   = (const float*)d_in[14];
    const float* bt2   = (const float*)d_in[15];
    const float* mu2   = (const float*)d_in[16];
    const float* va2   = (const float*)d_in[17];
    const float* w3    = (const float*)d_in[18];
    const float* cb3   = (const float*)d_in[19];
    const float* gm3   = (const float*)d_in[20];
    const float* bt3   = (const float*)d_in[21];
    const float* mu3   = (const float*)d_in[22];
    const float* va3   = (const float*)d_in[23];
    const float* w4    = (const float*)d_in[24];
    const float* b4    = (const float*)d_in[25];
    float* out = (float*)d_out;

    const int attn_smem = S * DH * 2 * (int)sizeof(float);            // 65536
    const int mlp_smem  = (32 * PCS + 32 * H2S + 32 * H3S + 4096 + 384 + 32) * (int)sizeof(float);

    cudaFuncSetAttribute(attn_kernel, cudaFuncAttributeMaxDynamicSharedMemorySize, attn_smem);
    cudaFuncSetAttribute(mlp_kernel,  cudaFuncAttributeMaxDynamicSharedMemorySize, mlp_smem);

    prep_kernel<<<1, 256>>>(npc);
    xqkv_kernel<<<dim3(S / 8, B), 256>>>(gl, cent, fc1w, fc1b, fc2w, fc2b, inw, inb);
    attn_kernel<<<dim3(S / 64, H, B), 64, attn_smem>>>();
    outproj_kernel<<<dim3(S / 8, B), 256>>>(ow, ob);
    mlp_kernel<<<dim3(NN / 32, B), 512, mlp_smem>>>(lo, w2, cb2, gm2, bt2, mu2, va2,
                                                    w3, cb3, gm3, bt3, mu3, va3,
                                                    w4, b4, out);
}

// round 3
// speedup vs baseline: 1.3281x; 1.3281x over previous
#include <cuda_runtime.h>
#include <math.h>

#define B 4
#define S 256
#define E 256
#define H 8
#define DH 32
#define LD 128
#define NN 65536
#define NC 2
#define EPS 1e-5f

// ---------------- scratch ----------------
__device__ __align__(16) float g_q[B*H*S*DH];
__device__ __align__(16) float g_k[B*H*S*DH];
__device__ __align__(16) float g_v[B*H*S*DH];
__device__ __align__(16) float g_ctx[B*S*E];
__device__ __align__(16) float g_attn[B*S*E];
__device__ __align__(16) float g_x[B*S*E];
__device__ int g_pref[S + 1];

// ---------------- f32x2 helpers ----------------
__device__ __forceinline__ void lds_v2(unsigned long long &a, unsigned long long &b, unsigned addr) {
    asm volatile("ld.shared.v2.u64 {%0,%1},[%2];" : "=l"(a), "=l"(b) : "r"(addr));
}
__device__ __forceinline__ void ffma2(unsigned long long &d, unsigned long long a, unsigned long long b) {
    asm("fma.rn.f32x2 %0, %1, %2, %0;" : "+l"(d) : "l"(a), "l"(b));
}
__device__ __forceinline__ void sts_dup(unsigned addr, float v) {
    asm volatile("st.shared.v2.b32 [%0],{%1,%1};" :: "r"(addr), "f"(v));
}
__device__ __forceinline__ void sts_v4(unsigned addr, float a, float b, float c, float d) {
    asm volatile("st.shared.v4.b32 [%0],{%1,%2,%3,%4};" :: "r"(addr), "f"(a), "f"(b), "f"(c), "f"(d));
}
__device__ __forceinline__ void sts_v2(unsigned addr, float a, float b) {
    asm volatile("st.shared.v2.b32 [%0],{%1,%2};" :: "r"(addr), "f"(a), "f"(b));
}
__device__ __forceinline__ void unpack2(unsigned long long v, float &lo, float &hi) {
    asm("mov.b64 {%0,%1},%2;" : "=f"(lo), "=f"(hi) : "l"(v));
}

// ---------------- kernel 1: prefix sums of np_cluster ----------------
__global__ void prep_kernel(const int* __restrict__ npc) {
    __shared__ int vals[S];
    int t = threadIdx.x;
    vals[t] = npc[t];
    __syncthreads();
    if (t == 0) {
        int a = 0;
        for (int s = 0; s < S; s++) { g_pref[s] = a; a += vals[s]; }
        g_pref[S] = a;
    }
}

// ---------------- kernel 2: x = gl^T + pos(centroids), grid (S,B) x 256 ----------------
__global__ void xk_kernel(const float* __restrict__ gl, const float* __restrict__ cent,
                          const float* __restrict__ fc1w, const float* __restrict__ fc1b,
                          const float* __restrict__ fc2w, const float* __restrict__ fc2b) {
    const int s = blockIdx.x, b = blockIdx.y, e = threadIdx.x;
    const float c0 = cent[(b * S + s) * 2 + 0];
    const float c1 = cent[(b * S + s) * 2 + 1];
    float pos = fc2b[e];
#pragma unroll
    for (int j = 0; j < 16; j++) {
        float hh = fc1b[j] + c0 * fc1w[2 * j] + c1 * fc1w[2 * j + 1];
        hh = (hh >= 0.f) ? hh : 0.01f * hh;
        pos += hh * fc2w[e * 16 + j];
    }
    g_x[(b * S + s) * E + e] = gl[(s * B + b) * E + e] + pos;
}

// ---------------- kernel 3: qkv = x @ Win^T + b,  grid (12 chunks, 8 stiles, B) x 256 ----------------
// out-tile 64, s-tile 32, K=256. ws stride 268 floats (4-phase LDS.128), xs stride 260.
__global__ void xqkv_kernel(const float* __restrict__ inw, const float* __restrict__ inb) {
    extern __shared__ float sh[];
    float* xs = sh;           // 32*260 = 8320
    float* ws = sh + 8320;    // 64*268 = 17152
    const int t = threadIdx.x;
    const int chunk = blockIdx.x, stile = blockIdx.y, b = blockIdx.z;
    const int s0 = stile * 32;

    // load xs: 2048 float4
    for (int p = 0; p < 8; p++) {
        int i4 = t + p * 256;
        int s = i4 >> 6, e4 = i4 & 63;
        *(float4*)&xs[s * 260 + 4 * e4] = *(const float4*)&g_x[(b * S + s0 + s) * E + 4 * e4];
    }
    // load ws: 4096 float4
    for (int p = 0; p < 16; p++) {
        int i4 = t + p * 256;
        int o = i4 >> 6, k4 = i4 & 63;
        *(float4*)&ws[o * 268 + 4 * k4] = *(const float4*)&inw[(chunk * 64 + o) * 256 + 4 * k4];
    }
    __syncthreads();

    const int ol = t & 63, sb = (t >> 6) * 8;
    float acc[8];
#pragma unroll
    for (int i = 0; i < 8; i++) acc[i] = 0.f;
#pragma unroll 8
    for (int k4 = 0; k4 < 64; k4++) {
        float4 wv = *(float4*)&ws[ol * 268 + 4 * k4];
#pragma unroll
        for (int i = 0; i < 8; i++) {
            float4 av = *(float4*)&xs[(sb + i) * 260 + 4 * k4];
            acc[i] += wv.x * av.x + wv.y * av.y + wv.z * av.z + wv.w * av.w;
        }
    }
    const int og = chunk * 64 + ol;
    const float bb = inb[og];
    const int part = og >> 8, e = og & 255, hh = e >> 5, d = e & 31;
    float* dst = (part == 0) ? g_q : ((part == 1) ? g_k : g_v);
#pragma unroll
    for (int i = 0; i < 8; i++) {
        int s = s0 + sb + i;
        dst[((b * H + hh) * S + s) * DH + d] = acc[i] + bb;
    }
}

// ---------------- kernel 4: attention, 4-way j-split online softmax, grid (4, H, B) x 256 ----------------
__global__ void attn_kernel() {
    extern __shared__ float sh[];
    float* ks  = sh;                 // 8192
    float* vs  = sh + 8192;          // 8192
    float* pm  = vs + 8192;          // 256
    float* pl  = pm + 256;           // 256
    float* pac = pl + 256;           // 4*64*33 = 8448
    const int t = threadIdx.x;
    const int b = blockIdx.z, h = blockIdx.y;
    const int base = ((b * H + h) * S) * DH;
    for (int i = t; i < 2048; i += 256) {
        ((float4*)ks)[i] = ((const float4*)(g_k + base))[i];
        ((float4*)vs)[i] = ((const float4*)(g_v + base))[i];
    }
    __syncthreads();
    const int q = t & 63, jh = t >> 6;
    const int qg = blockIdx.x * 64 + q;
    float qr[DH];
#pragma unroll
    for (int i = 0; i < 8; i++) ((float4*)qr)[i] = ((const float4*)(g_q + base + qg * DH))[i];
    const float scale = 0.17677669529663687f;
    float m = -1e30f, l = 0.f, acc[DH];
#pragma unroll
    for (int d = 0; d < DH; d++) acc[d] = 0.f;
    for (int j = jh * 64; j < jh * 64 + 64; j++) {
        float sc = 0.f;
#pragma unroll
        for (int d = 0; d < DH; d++) sc += qr[d] * ks[j * DH + d];
        sc *= scale;
        float mn = fmaxf(m, sc);
        float corr = __expf(m - mn);
        float p = __expf(sc - mn);
        m = mn;
        l = l * corr + p;
#pragma unroll
        for (int d = 0; d < DH; d++) acc[d] = acc[d] * corr + p * vs[j * DH + d];
    }
    pm[jh * 64 + q] = m;
    pl[jh * 64 + q] = l;
#pragma unroll
    for (int d = 0; d < DH; d++) pac[(jh * 64 + q) * 33 + d] = acc[d];
    __syncthreads();
    if (t < 64) {
        float M = pm[t];
#pragma unroll
        for (int i = 1; i < 4; i++) M = fmaxf(M, pm[i * 64 + t]);
        float e0 = __expf(pm[t] - M), e1 = __expf(pm[64 + t] - M),
              e2 = __expf(pm[128 + t] - M), e3 = __expf(pm[192 + t] - M);
        float L = pl[t] * e0 + pl[64 + t] * e1 + pl[128 + t] * e2 + pl[192 + t] * e3;
        float inv = 1.f / L;
        int qo = blockIdx.x * 64 + t;
#pragma unroll
        for (int d = 0; d < DH; d++) {
            float v = pac[t * 33 + d] * e0 + pac[(64 + t) * 33 + d] * e1 +
                      pac[(128 + t) * 33 + d] * e2 + pac[(192 + t) * 33 + d] * e3;
            g_ctx[(b * S + qo) * E + h * DH + d] = v * inv;
        }
    }
}

// ---------------- kernel 5: out_proj, grid (8 chunks, 8 stiles, B) x 256 ----------------
__global__ void outproj_kernel(const float* __restrict__ ow, const float* __restrict__ ob) {
    extern __shared__ float sh[];
    float* cs = sh;          // 32*260 = 8320
    float* ws = sh + 8320;   // 32*268 = 8576
    const int t = threadIdx.x;
    const int chunk = blockIdx.x, stile = blockIdx.y, b = blockIdx.z;
    const int s0 = stile * 32;
    for (int p = 0; p < 8; p++) {
        int i4 = t + p * 256;
        int s = i4 >> 6, e4 = i4 & 63;
        *(float4*)&cs[s * 260 + 4 * e4] = *(const float4*)&g_ctx[(b * S + s0 + s) * E + 4 * e4];
    }
    for (int p = 0; p < 8; p++) {
        int i4 = t + p * 256;
        int o = i4 >> 6, k4 = i4 & 63;
        *(float4*)&ws[o * 268 + 4 * k4] = *(const float4*)&ow[(chunk * 32 + o) * 256 + 4 * k4];
    }
    __syncthreads();
    const int ol = t & 31, sb = (t >> 5) * 4;
    float acc[4] = {0.f, 0.f, 0.f, 0.f};
#pragma unroll 8
    for (int k4 = 0; k4 < 64; k4++) {
        float4 wv = *(float4*)&ws[ol * 268 + 4 * k4];
#pragma unroll
        for (int i = 0; i < 4; i++) {
            float4 av = *(float4*)&cs[(sb + i) * 260 + 4 * k4];
            acc[i] += wv.x * av.x + wv.y * av.y + wv.z * av.z + wv.w * av.w;
        }
    }
    const int og = chunk * 32 + ol;
    const float bb = ob[og];
#pragma unroll
    for (int i = 0; i < 4; i++)
        g_attn[(b * S + s0 + sb + i) * E + og] = acc[i] + bb;
}

// ---------------- kernel 6: fused point-MLP with f32x2 packed pairs ----------------
// PT=64 points (32 pairs), 512 threads (16 warps). Pair-packed activations in smem,
// duplicated (w,w) weight tiles. All LDS.128 strides hit the 4-phase minimum.
#define PA_S  386   // float2 stride, pair rows (2*386 mod 32 == 4 -> 4 phases; 386*8 mult 16)
#define WD_S  34    // wdup stride stage1
#define H2_S  130   // h2 packed stride
#define W3_S  66    // wdup stride stage2 / h3 stride

#define OFF_PA   0
#define OFF_WD   24704                // 32*386*2
#define OFF_H2   (OFF_WD + 8704)     // 128*34*2
#define OFF_H3   (OFF_H2 + 8320)     // 32*130*2
#define OFF_SC2  (OFF_H3 + 4224)     // 32*66*2
#define OFF_BI2  (OFF_SC2 + 128)
#define OFF_SC3  (OFF_BI2 + 128)
#define OFF_BI3  (OFF_SC3 + 64)
#define OFF_PREF (OFF_BI3 + 64)      // 257 ints
#define OFF_CID  (OFF_PREF + 257)    // 64 ints
#define MLP_FLOATS (OFF_CID + 64)

__global__ __launch_bounds__(512, 1)
void mlp_kernel(const float* __restrict__ lo,
                const float* __restrict__ w2, const float* __restrict__ cb2,
                const float* __restrict__ gm2, const float* __restrict__ bt2,
                const float* __restrict__ mu2, const float* __restrict__ va2,
                const float* __restrict__ w3, const float* __restrict__ cb3,
                const float* __restrict__ gm3, const float* __restrict__ bt3,
                const float* __restrict__ mu3, const float* __restrict__ va3,
                const float* __restrict__ w4, const float* __restrict__ b4,
                float* __restrict__ out) {
    extern __shared__ float sm[];
    int* pref = (int*)(sm + OFF_PREF);
    int* cid  = (int*)(sm + OFF_CID);
    const unsigned smemB = (unsigned)__cvta_generic_to_shared(sm);
    const unsigned paB = smemB + OFF_PA * 4;
    const unsigned wdB = smemB + OFF_WD * 4;
    const unsigned h2B = smemB + OFF_H2 * 4;
    const unsigned h3B = smemB + OFF_H3 * 4;

    const int t = threadIdx.x;
    const int b = blockIdx.y;
    const int n0 = blockIdx.x * 64;
    const int w = t >> 5, l = t & 31;

    // phase 0: fold bn, load prefix
    if (t < 257) pref[t] = g_pref[t];
    if (t >= 288 && t < 416) {
        int c = t - 288;
        float s = gm2[c] * rsqrtf(va2[c] + EPS);
        sm[OFF_SC2 + c] = s;
        sm[OFF_BI2 + c] = (cb2[c] - mu2[c]) * s + bt2[c];
    }
    if (t >= 416 && t < 480) {
        int c = t - 416;
        float s = gm3[c] * rsqrtf(va3[c] + EPS);
        sm[OFF_SC3 + c] = s;
        sm[OFF_BI3 + c] = (cb3[c] - mu3[c]) * s + bt3[c];
    }
    __syncthreads();
    if (t < 64) {
        int i = n0 + t;
        int s = 0;
#pragma unroll
        for (int step = 128; step >= 1; step >>= 1)
            if (s + step <= 255 && pref[s + step] <= i) s += step;
        cid[t] = s;
    }
    __syncthreads();

    // stage-1 weight prefetch regs (2 rows per thread: ch, ch+64 at k4 quad)
    const int wch = t >> 3, wk4 = t & 7;
    const float sA = sm[OFF_SC2 + wch], sB = sm[OFF_SC2 + wch + 64];
    float4 wra = *(const float4*)&w2[wch * 384 + 4 * wk4];
    float4 wrb = *(const float4*)&w2[(wch + 64) * 384 + 4 * wk4];

    // gather pair-packed activations: warp -> pairs {w, w+16}, lane -> 2 k's
    for (int rep = 0; rep < 2; rep++) {
        const int pr = w + rep * 16;
        const int p0 = n0 + 2 * pr, p1 = p0 + 1;
        const int q0 = cid[2 * pr], q1 = cid[2 * pr + 1];
        const float* lo0 = lo + (size_t)(b * NN + p0) * LD;
        const float* lo1 = lo + (size_t)(b * NN + p1) * LD;
        const float* at0 = g_attn + (b * S + q0) * E;
        const float* at1 = g_attn + (b * S + q1) * E;
#pragma unroll
        for (int pass = 0; pass < 6; pass++) {
            int k = pass * 64 + 2 * l;
            float2 v0, v1;
            if (k < 128) { v0 = *(const float2*)(lo0 + k); v1 = *(const float2*)(lo1 + k); }
            else         { v0 = *(const float2*)(at0 + k - 128); v1 = *(const float2*)(at1 + k - 128); }
            sts_v4(paB + (unsigned)(pr * PA_S + k) * 8u, v0.x, v1.x, v0.y, v1.y);
        }
    }

    // ---- stage 1: h2 = relu(pc @ W2fold^T + b2fold), 12 k-tiles of 32 ----
    const int c0 = w * 8;
    unsigned long long A[8];
#pragma unroll
    for (int j = 0; j < 8; j++) A[j] = 0ull;
    const unsigned wstA = wdB + (unsigned)(wch * WD_S + wk4 * 4) * 8u;
    const unsigned wstB = wdB + (unsigned)((wch + 64) * WD_S + wk4 * 4) * 8u;
    const unsigned wrdB = wdB + (unsigned)(c0 * WD_S) * 8u;

    for (int ti = 0; ti < 12; ti++) {
        sts_dup(wstA + 0,  wra.x * sA); sts_dup(wstA + 8,  wra.y * sA);
        sts_dup(wstA + 16, wra.z * sA); sts_dup(wstA + 24, wra.w * sA);
        sts_dup(wstB + 0,  wrb.x * sB); sts_dup(wstB + 8,  wrb.y * sB);
        sts_dup(wstB + 16, wrb.z * sB); sts_dup(wstB + 24, wrb.w * sB);
        __syncthreads();
        if (ti + 1 < 12) {
            int kt = (ti + 1) * 32;
            wra = *(const float4*)&w2[wch * 384 + kt + 4 * wk4];
            wrb = *(const float4*)&w2[(wch + 64) * 384 + kt + 4 * wk4];
        }
        const unsigned aaddr = paB + (unsigned)(l * PA_S + ti * 32) * 8u;
#pragma unroll
        for (int kk = 0; kk < 32; kk += 2) {
            unsigned long long a0, a1;
            lds_v2(a0, a1, aaddr + kk * 8u);
#pragma unroll
            for (int j = 0; j < 8; j++) {
                unsigned long long w0, w1;
                lds_v2(w0, w1, wrdB + (unsigned)(j * WD_S + kk) * 8u);
                ffma2(A[j], a0, w0);
                ffma2(A[j], a1, w1);
            }
        }
        __syncthreads();
    }
    // epilogue: bias + relu + packed store to h2
#pragma unroll
    for (int j = 0; j < 8; j++) {
        float e0, e1;
        unpack2(A[j], e0, e1);
        float bi = sm[OFF_BI2 + c0 + j];
        e0 = fmaxf(e0 + bi, 0.f);
        e1 = fmaxf(e1 + bi, 0.f);
        sts_v2(h2B + (unsigned)(l * H2_S + c0 + j) * 8u, e0, e1);
    }

    // stage-2 prefetch (2 rows per thread: ch, ch+32 of W3 at k4 quad)
    const int xch = t >> 4, xk4 = t & 15;
    const float s3A = sm[OFF_SC3 + xch], s3B = sm[OFF_SC3 + xch + 32];
    float4 xra = *(const float4*)&w3[xch * 128 + 4 * xk4];
    float4 xrb = *(const float4*)&w3[(xch + 32) * 128 + 4 * xk4];
    __syncthreads();   // h2 complete, wdup free

    // ---- stage 2: h3 = relu(h2 @ W3fold^T + b3fold), 2 k-tiles of 64 ----
    const int c2 = w * 4;
    unsigned long long C[4];
#pragma unroll
    for (int j = 0; j < 4; j++) C[j] = 0ull;
    const unsigned xstA = wdB + (unsigned)(xch * W3_S + xk4 * 4) * 8u;
    const unsigned xstB = wdB + (unsigned)((xch + 32) * W3_S + xk4 * 4) * 8u;
    const unsigned xrdB = wdB + (unsigned)(c2 * W3_S) * 8u;

    for (int ti = 0; ti < 2; ti++) {
        sts_dup(xstA + 0,  xra.x * s3A); sts_dup(xstA + 8,  xra.y * s3A);
        sts_dup(xstA + 16, xra.z * s3A); sts_dup(xstA + 24, xra.w * s3A);
        sts_dup(xstB + 0,  xrb.x * s3B); sts_dup(xstB + 8,  xrb.y * s3B);
        sts_dup(xstB + 16, xrb.z * s3B); sts_dup(xstB + 24, xrb.w * s3B);
        __syncthreads();
        if (ti == 0) {
            xra = *(const float4*)&w3[xch * 128 + 64 + 4 * xk4];
            xrb = *(const float4*)&w3[(xch + 32) * 128 + 64 + 4 * xk4];
        }
        const unsigned aaddr = h2B + (unsigned)(l * H2_S + ti * 64) * 8u;
#pragma unroll
        for (int kk = 0; kk < 64; kk += 2) {
            unsigned long long a0, a1;
            lds_v2(a0, a1, aaddr + kk * 8u);
#pragma unroll
            for (int j = 0; j < 4; j++) {
                unsigned long long w0, w1;
                lds_v2(w0, w1, xrdB + (unsigned)(j * W3_S + kk) * 8u);
                ffma2(C[j], a0, w0);
                ffma2(C[j], a1, w1);
            }
        }
        __syncthreads();
    }
#pragma unroll
    for (int j = 0; j < 4; j++) {
        float e0, e1;
        unpack2(C[j], e0, e1);
        float bi = sm[OFF_BI3 + c2 + j];
        e0 = fmaxf(e0 + bi, 0.f);
        e1 = fmaxf(e1 + bi, 0.f);
        sts_v2(h3B + (unsigned)(l * W3_S + c2 + j) * 8u, e0, e1);
    }
    __syncthreads();

    // ---- stage 3: out = h3 @ W4^T + b4, transposed write ----
    if (t < 128) {
        const int p = t >> 1, c = t & 1;
        const float* h3f = sm + OFF_H3;
        const int pb = (p >> 1) * (2 * W3_S), par = p & 1;
        float a = b4[c];
#pragma unroll
        for (int k = 0; k < 64; k++)
            a += h3f[pb + 2 * k + par] * __ldg(&w4[c * 64 + k]);
        out[(b * NC + c) * NN + n0 + p] = a;
    }
}

// ---------------- launch ----------------
extern "C" void kernel_launch(void* const* d_in, const int* in_sizes, int n_in,
                              void* d_out, int out_size) {
    const float* gl   = (const float*)d_in[0];
    const float* lo   = (const float*)d_in[1];
    const float* cent = (const float*)d_in[2];
    const int*   npc  = (const int*)  d_in[3];
    const float* fc1w = (const float*)d_in[4];
    const float* fc1b = (const float*)d_in[5];
    const float* fc2w = (const float*)d_in[6];
    const float* fc2b = (const float*)d_in[7];
    const float* inw  = (const float*)d_in[8];
    const float* inb  = (const float*)d_in[9];
    const float* ow   = (const float*)d_in[10];
    const float* ob   = (const float*)d_in[11];
    const float* w2   = (const float*)d_in[12];
    const float* cb2  = (const float*)d_in[13];
    const float* gm2  = (const float*)d_in[14];
    const float* bt2  = (const float*)d_in[15];
    const float* mu2  = (const float*)d_in[16];
    const float* va2  = (const float*)d_in[17];
    const float* w3   = (const float*)d_in[18];
    const float* cb3  = (const float*)d_in[19];
    const float* gm3  = (const float*)d_in[20];
    const float* bt3  = (const float*)d_in[21];
    const float* mu3  = (const float*)d_in[22];
    const float* va3  = (const float*)d_in[23];
    const float* w4   = (const float*)d_in[24];
    const float* b4   = (const float*)d_in[25];
    float* out = (float*)d_out;

    const int xqkv_smem = (8320 + 17152) * 4;            // 101,888
    const int attn_smem = (8192 * 2 + 256 * 2 + 8448) * 4; // 101,376
    const int outp_smem = (8320 + 8576) * 4;             // 67,584
    const int mlp_smem  = MLP_FLOATS * 4;                // ~186.6 KB

    cudaFuncSetAttribute(xqkv_kernel,   cudaFuncAttributeMaxDynamicSharedMemorySize, xqkv_smem);
    cudaFuncSetAttribute(attn_kernel,   cudaFuncAttributeMaxDynamicSharedMemorySize, attn_smem);
    cudaFuncSetAttribute(outproj_kernel,cudaFuncAttributeMaxDynamicSharedMemorySize, outp_smem);
    cudaFuncSetAttribute(mlp_kernel,    cudaFuncAttributeMaxDynamicSharedMemorySize, mlp_smem);

    prep_kernel<<<1, 256>>>(npc);
    xk_kernel<<<dim3(S, B), 256>>>(gl, cent, fc1w, fc1b, fc2w, fc2b);
    xqkv_kernel<<<dim3(12, 8, B), 256, xqkv_smem>>>(inw, inb);
    attn_kernel<<<dim3(4, H, B), 256, attn_smem>>>();
    outproj_kernel<<<dim3(8, 8, B), 256, outp_smem>>>(ow, ob);
    mlp_kernel<<<dim3(NN / 64, B), 512, mlp_smem>>>(lo, w2, cb2, gm2, bt2, mu2, va2,
                                                    w3, cb3, gm3, bt3, mu3, va3,
                                                    w4, b4, out);
}

// round 4
// speedup vs baseline: 1.3392x; 1.0084x over previous
#include <cuda_runtime.h>
#include <math.h>

#define B 4
#define S 256
#define E 256
#define H 8
#define DH 32
#define LD 128
#define NN 65536
#define NC 2
#define EPS 1e-5f

// ---------------- scratch ----------------
__device__ __align__(16) float g_q[B*H*S*DH];
__device__ __align__(16) float g_k[B*H*S*DH];
__device__ __align__(16) float g_v[B*H*S*DH];
__device__ __align__(16) float g_ctx[B*S*E];
__device__ __align__(16) float g_attn[B*S*E];
__device__ __align__(16) float g_x[B*S*E];
__device__ int g_pref[S + 1];

// ---------------- f32x2 helpers ----------------
__device__ __forceinline__ void lds_v2(unsigned long long &a, unsigned long long &b, unsigned addr) {
    asm volatile("ld.shared.v2.u64 {%0,%1},[%2];" : "=l"(a), "=l"(b) : "r"(addr));
}
__device__ __forceinline__ void ffma2(unsigned long long &d, unsigned long long a, unsigned long long b) {
    asm("fma.rn.f32x2 %0, %1, %2, %0;" : "+l"(d) : "l"(a), "l"(b));
}
__device__ __forceinline__ void sts_dup(unsigned addr, float v) {
    asm volatile("st.shared.v2.b32 [%0],{%1,%1};" :: "r"(addr), "f"(v));
}
__device__ __forceinline__ void sts_v4(unsigned addr, float a, float b, float c, float d) {
    asm volatile("st.shared.v4.b32 [%0],{%1,%2,%3,%4};" :: "r"(addr), "f"(a), "f"(b), "f"(c), "f"(d));
}
__device__ __forceinline__ void sts_v2(unsigned addr, float a, float b) {
    asm volatile("st.shared.v2.b32 [%0],{%1,%2};" :: "r"(addr), "f"(a), "f"(b));
}
__device__ __forceinline__ void unpack2(unsigned long long v, float &lo, float &hi) {
    asm("mov.b64 {%0,%1},%2;" : "=f"(lo), "=f"(hi) : "l"(v));
}

// ---------------- kernel 1: prefix sums of np_cluster ----------------
__global__ void prep_kernel(const int* __restrict__ npc) {
    __shared__ int vals[S];
    int t = threadIdx.x;
    vals[t] = npc[t];
    __syncthreads();
    if (t == 0) {
        int a = 0;
        for (int s = 0; s < S; s++) { g_pref[s] = a; a += vals[s]; }
        g_pref[S] = a;
    }
}

// ---------------- kernel 2: x = gl^T + pos(centroids), grid (S,B) x 256 ----------------
__global__ void xk_kernel(const float* __restrict__ gl, const float* __restrict__ cent,
                          const float* __restrict__ fc1w, const float* __restrict__ fc1b,
                          const float* __restrict__ fc2w, const float* __restrict__ fc2b) {
    const int s = blockIdx.x, b = blockIdx.y, e = threadIdx.x;
    const float c0 = cent[(b * S + s) * 2 + 0];
    const float c1 = cent[(b * S + s) * 2 + 1];
    float pos = fc2b[e];
#pragma unroll
    for (int j = 0; j < 16; j++) {
        float hh = fc1b[j] + c0 * fc1w[2 * j] + c1 * fc1w[2 * j + 1];
        hh = (hh >= 0.f) ? hh : 0.01f * hh;
        pos += hh * fc2w[e * 16 + j];
    }
    g_x[(b * S + s) * E + e] = gl[(s * B + b) * E + e] + pos;
}

// ---------------- kernel 3: qkv = x @ Win^T + b,  grid (12 chunks, 8 stiles, B) x 256 ----------------
// out-tile 64, s-tile 32, K=256. ws stride 268 floats (4-phase LDS.128), xs stride 260.
__global__ void xqkv_kernel(const float* __restrict__ inw, const float* __restrict__ inb) {
    extern __shared__ float sh[];
    float* xs = sh;           // 32*260 = 8320
    float* ws = sh + 8320;    // 64*268 = 17152
    const int t = threadIdx.x;
    const int chunk = blockIdx.x, stile = blockIdx.y, b = blockIdx.z;
    const int s0 = stile * 32;

    // load xs: 2048 float4
    for (int p = 0; p < 8; p++) {
        int i4 = t + p * 256;
        int s = i4 >> 6, e4 = i4 & 63;
        *(float4*)&xs[s * 260 + 4 * e4] = *(const float4*)&g_x[(b * S + s0 + s) * E + 4 * e4];
    }
    // load ws: 4096 float4
    for (int p = 0; p < 16; p++) {
        int i4 = t + p * 256;
        int o = i4 >> 6, k4 = i4 & 63;
        *(float4*)&ws[o * 268 + 4 * k4] = *(const float4*)&inw[(chunk * 64 + o) * 256 + 4 * k4];
    }
    __syncthreads();

    const int ol = t & 63, sb = (t >> 6) * 8;
    float acc[8];
#pragma unroll
    for (int i = 0; i < 8; i++) acc[i] = 0.f;
#pragma unroll 8
    for (int k4 = 0; k4 < 64; k4++) {
        float4 wv = *(float4*)&ws[ol * 268 + 4 * k4];
#pragma unroll
        for (int i = 0; i < 8; i++) {
            float4 av = *(float4*)&xs[(sb + i) * 260 + 4 * k4];
            acc[i] += wv.x * av.x + wv.y * av.y + wv.z * av.z + wv.w * av.w;
        }
    }
    const int og = chunk * 64 + ol;
    const float bb = inb[og];
    const int part = og >> 8, e = og & 255, hh = e >> 5, d = e & 31;
    float* dst = (part == 0) ? g_q : ((part == 1) ? g_k : g_v);
#pragma unroll
    for (int i = 0; i < 8; i++) {
        int s = s0 + sb + i;
        dst[((b * H + hh) * S + s) * DH + d] = acc[i] + bb;
    }
}

// ---------------- kernel 4: attention, 4-way j-split online softmax, grid (4, H, B) x 256 ----------------
__global__ void attn_kernel() {
    extern __shared__ float sh[];
    float* ks  = sh;                 // 8192
    float* vs  = sh + 8192;          // 8192
    float* pm  = vs + 8192;          // 256
    float* pl  = pm + 256;           // 256
    float* pac = pl + 256;           // 4*64*33 = 8448
    const int t = threadIdx.x;
    const int b = blockIdx.z, h = blockIdx.y;
    const int base = ((b * H + h) * S) * DH;
    for (int i = t; i < 2048; i += 256) {
        ((float4*)ks)[i] = ((const float4*)(g_k + base))[i];
        ((float4*)vs)[i] = ((const float4*)(g_v + base))[i];
    }
    __syncthreads();
    const int q = t & 63, jh = t >> 6;
    const int qg = blockIdx.x * 64 + q;
    float qr[DH];
#pragma unroll
    for (int i = 0; i < 8; i++) ((float4*)qr)[i] = ((const float4*)(g_q + base + qg * DH))[i];
    const float scale = 0.17677669529663687f;
    float m = -1e30f, l = 0.f, acc[DH];
#pragma unroll
    for (int d = 0; d < DH; d++) acc[d] = 0.f;
    for (int j = jh * 64; j < jh * 64 + 64; j++) {
        float sc = 0.f;
#pragma unroll
        for (int d = 0; d < DH; d++) sc += qr[d] * ks[j * DH + d];
        sc *= scale;
        float mn = fmaxf(m, sc);
        float corr = __expf(m - mn);
        float p = __expf(sc - mn);
        m = mn;
        l = l * corr + p;
#pragma unroll
        for (int d = 0; d < DH; d++) acc[d] = acc[d] * corr + p * vs[j * DH + d];
    }
    pm[jh * 64 + q] = m;
    pl[jh * 64 + q] = l;
#pragma unroll
    for (int d = 0; d < DH; d++) pac[(jh * 64 + q) * 33 + d] = acc[d];
    __syncthreads();
    if (t < 64) {
        float M = pm[t];
#pragma unroll
        for (int i = 1; i < 4; i++) M = fmaxf(M, pm[i * 64 + t]);
        float e0 = __expf(pm[t] - M), e1 = __expf(pm[64 + t] - M),
              e2 = __expf(pm[128 + t] - M), e3 = __expf(pm[192 + t] - M);
        float L = pl[t] * e0 + pl[64 + t] * e1 + pl[128 + t] * e2 + pl[192 + t] * e3;
        float inv = 1.f / L;
        int qo = blockIdx.x * 64 + t;
#pragma unroll
        for (int d = 0; d < DH; d++) {
            float v = pac[t * 33 + d] * e0 + pac[(64 + t) * 33 + d] * e1 +
                      pac[(128 + t) * 33 + d] * e2 + pac[(192 + t) * 33 + d] * e3;
            g_ctx[(b * S + qo) * E + h * DH + d] = v * inv;
        }
    }
}

// ---------------- kernel 5: out_proj, grid (8 chunks, 8 stiles, B) x 256 ----------------
__global__ void outproj_kernel(const float* __restrict__ ow, const float* __restrict__ ob) {
    extern __shared__ float sh[];
    float* cs = sh;          // 32*260 = 8320
    float* ws = sh + 8320;   // 32*268 = 8576
    const int t = threadIdx.x;
    const int chunk = blockIdx.x, stile = blockIdx.y, b = blockIdx.z;
    const int s0 = stile * 32;
    for (int p = 0; p < 8; p++) {
        int i4 = t + p * 256;
        int s = i4 >> 6, e4 = i4 & 63;
        *(float4*)&cs[s * 260 + 4 * e4] = *(const float4*)&g_ctx[(b * S + s0 + s) * E + 4 * e4];
    }
    for (int p = 0; p < 8; p++) {
        int i4 = t + p * 256;
        int o = i4 >> 6, k4 = i4 & 63;
        *(float4*)&ws[o * 268 + 4 * k4] = *(const float4*)&ow[(chunk * 32 + o) * 256 + 4 * k4];
    }
    __syncthreads();
    const int ol = t & 31, sb = (t >> 5) * 4;
    float acc[4] = {0.f, 0.f, 0.f, 0.f};
#pragma unroll 8
    for (int k4 = 0; k4 < 64; k4++) {
        float4 wv = *(float4*)&ws[ol * 268 + 4 * k4];
#pragma unroll
        for (int i = 0; i < 4; i++) {
            float4 av = *(float4*)&cs[(sb + i) * 260 + 4 * k4];
            acc[i] += wv.x * av.x + wv.y * av.y + wv.z * av.z + wv.w * av.w;
        }
    }
    const int og = chunk * 32 + ol;
    const float bb = ob[og];
#pragma unroll
    for (int i = 0; i < 4; i++)
        g_attn[(b * S + s0 + sb + i) * E + og] = acc[i] + bb;
}

// ---------------- kernel 6: fused point-MLP with f32x2 packed pairs ----------------
// PT=64 points (32 pairs), 512 threads (16 warps). Pair-packed activations in smem,
// duplicated (w,w) weight tiles. All LDS.128 strides hit the 4-phase minimum.
#define PA_S  386   // float2 stride, pair rows (2*386 mod 32 == 4 -> 4 phases; 386*8 mult 16)
#define WD_S  34    // wdup stride stage1
#define H2_S  130   // h2 packed stride
#define W3_S  66    // wdup stride stage2 / h3 stride

#define OFF_PA   0
#define OFF_WD   24704                // 32*386*2
#define OFF_H2   (OFF_WD + 8704)     // 128*34*2
#define OFF_H3   (OFF_H2 + 8320)     // 32*130*2
#define OFF_SC2  (OFF_H3 + 4224)     // 32*66*2
#define OFF_BI2  (OFF_SC2 + 128)
#define OFF_SC3  (OFF_BI2 + 128)
#define OFF_BI3  (OFF_SC3 + 64)
#define OFF_PREF (OFF_BI3 + 64)      // 257 ints
#define OFF_CID  (OFF_PREF + 257)    // 64 ints
#define MLP_FLOATS (OFF_CID + 64)

__global__ __launch_bounds__(512, 1)
void mlp_kernel(const float* __restrict__ lo,
                const float* __restrict__ w2, const float* __restrict__ cb2,
                const float* __restrict__ gm2, const float* __restrict__ bt2,
                const float* __restrict__ mu2, const float* __restrict__ va2,
                const float* __restrict__ w3, const float* __restrict__ cb3,
                const float* __restrict__ gm3, const float* __restrict__ bt3,
                const float* __restrict__ mu3, const float* __restrict__ va3,
                const float* __restrict__ w4, const float* __restrict__ b4,
                float* __restrict__ out) {
    extern __shared__ float sm[];
    int* pref = (int*)(sm + OFF_PREF);
    int* cid  = (int*)(sm + OFF_CID);
    const unsigned smemB = (unsigned)__cvta_generic_to_shared(sm);
    const unsigned paB = smemB + OFF_PA * 4;
    const unsigned wdB = smemB + OFF_WD * 4;
    const unsigned h2B = smemB + OFF_H2 * 4;
    const unsigned h3B = smemB + OFF_H3 * 4;

    const int t = threadIdx.x;
    const int b = blockIdx.y;
    const int n0 = blockIdx.x * 64;
    const int w = t >> 5, l = t & 31;

    // phase 0: fold bn, load prefix
    if (t < 257) pref[t] = g_pref[t];
    if (t >= 288 && t < 416) {
        int c = t - 288;
        float s = gm2[c] * rsqrtf(va2[c] + EPS);
        sm[OFF_SC2 + c] = s;
        sm[OFF_BI2 + c] = (cb2[c] - mu2[c]) * s + bt2[c];
    }
    if (t >= 416 && t < 480) {
        int c = t - 416;
        float s = gm3[c] * rsqrtf(va3[c] + EPS);
        sm[OFF_SC3 + c] = s;
        sm[OFF_BI3 + c] = (cb3[c] - mu3[c]) * s + bt3[c];
    }
    __syncthreads();
    if (t < 64) {
        int i = n0 + t;
        int s = 0;
#pragma unroll
        for (int step = 128; step >= 1; step >>= 1)
            if (s + step <= 255 && pref[s + step] <= i) s += step;
        cid[t] = s;
    }
    __syncthreads();

    // stage-1 weight prefetch regs (2 rows per thread: ch, ch+64 at k4 quad)
    const int wch = t >> 3, wk4 = t & 7;
    const float sA = sm[OFF_SC2 + wch], sB = sm[OFF_SC2 + wch + 64];
    float4 wra = *(const float4*)&w2[wch * 384 + 4 * wk4];
    float4 wrb = *(const float4*)&w2[(wch + 64) * 384 + 4 * wk4];

    // gather pair-packed activations: warp -> pairs {w, w+16}, lane -> 2 k's
    for (int rep = 0; rep < 2; rep++) {
        const int pr = w + rep * 16;
        const int p0 = n0 + 2 * pr, p1 = p0 + 1;
        const int q0 = cid[2 * pr], q1 = cid[2 * pr + 1];
        const float* lo0 = lo + (size_t)(b * NN + p0) * LD;
        const float* lo1 = lo + (size_t)(b * NN + p1) * LD;
        const float* at0 = g_attn + (b * S + q0) * E;
        const float* at1 = g_attn + (b * S + q1) * E;
#pragma unroll
        for (int pass = 0; pass < 6; pass++) {
            int k = pass * 64 + 2 * l;
            float2 v0, v1;
            if (k < 128) { v0 = *(const float2*)(lo0 + k); v1 = *(const float2*)(lo1 + k); }
            else         { v0 = *(const float2*)(at0 + k - 128); v1 = *(const float2*)(at1 + k - 128); }
            sts_v4(paB + (unsigned)(pr * PA_S + k) * 8u, v0.x, v1.x, v0.y, v1.y);
        }
    }

    // ---- stage 1: h2 = relu(pc @ W2fold^T + b2fold), 12 k-tiles of 32 ----
    const int c0 = w * 8;
    unsigned long long A[8];
#pragma unroll
    for (int j = 0; j < 8; j++) A[j] = 0ull;
    const unsigned wstA = wdB + (unsigned)(wch * WD_S + wk4 * 4) * 8u;
    const unsigned wstB = wdB + (unsigned)((wch + 64) * WD_S + wk4 * 4) * 8u;
    const unsigned wrdB = wdB + (unsigned)(c0 * WD_S) * 8u;

    for (int ti = 0; ti < 12; ti++) {
        sts_dup(wstA + 0,  wra.x * sA); sts_dup(wstA + 8,  wra.y * sA);
        sts_dup(wstA + 16, wra.z * sA); sts_dup(wstA + 24, wra.w * sA);
        sts_dup(wstB + 0,  wrb.x * sB); sts_dup(wstB + 8,  wrb.y * sB);
        sts_dup(wstB + 16, wrb.z * sB); sts_dup(wstB + 24, wrb.w * sB);
        __syncthreads();
        if (ti + 1 < 12) {
            int kt = (ti + 1) * 32;
            wra = *(const float4*)&w2[wch * 384 + kt + 4 * wk4];
            wrb = *(const float4*)&w2[(wch + 64) * 384 + kt + 4 * wk4];
        }
        const unsigned aaddr = paB + (unsigned)(l * PA_S + ti * 32) * 8u;
#pragma unroll
        for (int kk = 0; kk < 32; kk += 2) {
            unsigned long long a0, a1;
            lds_v2(a0, a1, aaddr + kk * 8u);
#pragma unroll
            for (int j = 0; j < 8; j++) {
                unsigned long long w0, w1;
                lds_v2(w0, w1, wrdB + (unsigned)(j * WD_S + kk) * 8u);
                ffma2(A[j], a0, w0);
                ffma2(A[j], a1, w1);
            }
        }
        __syncthreads();
    }
    // epilogue: bias + relu + packed store to h2
#pragma unroll
    for (int j = 0; j < 8; j++) {
        float e0, e1;
        unpack2(A[j], e0, e1);
        float bi = sm[OFF_BI2 + c0 + j];
        e0 = fmaxf(e0 + bi, 0.f);
        e1 = fmaxf(e1 + bi, 0.f);
        sts_v2(h2B + (unsigned)(l * H2_S + c0 + j) * 8u, e0, e1);
    }

    // stage-2 prefetch (2 rows per thread: ch, ch+32 of W3 at k4 quad)
    const int xch = t >> 4, xk4 = t & 15;
    const float s3A = sm[OFF_SC3 + xch], s3B = sm[OFF_SC3 + xch + 32];
    float4 xra = *(const float4*)&w3[xch * 128 + 4 * xk4];
    float4 xrb = *(const float4*)&w3[(xch + 32) * 128 + 4 * xk4];
    __syncthreads();   // h2 complete, wdup free

    // ---- stage 2: h3 = relu(h2 @ W3fold^T + b3fold), 2 k-tiles of 64 ----
    const int c2 = w * 4;
    unsigned long long C[4];
#pragma unroll
    for (int j = 0; j < 4; j++) C[j] = 0ull;
    const unsigned xstA = wdB + (unsigned)(xch * W3_S + xk4 * 4) * 8u;
    const unsigned xstB = wdB + (unsigned)((xch + 32) * W3_S + xk4 * 4) * 8u;
    const unsigned xrdB = wdB + (unsigned)(c2 * W3_S) * 8u;

    for (int ti = 0; ti < 2; ti++) {
        sts_dup(xstA + 0,  xra.x * s3A); sts_dup(xstA + 8,  xra.y * s3A);
        sts_dup(xstA + 16, xra.z * s3A); sts_dup(xstA + 24, xra.w * s3A);
        sts_dup(xstB + 0,  xrb.x * s3B); sts_dup(xstB + 8,  xrb.y * s3B);
        sts_dup(xstB + 16, xrb.z * s3B); sts_dup(xstB + 24, xrb.w * s3B);
        __syncthreads();
        if (ti == 0) {
            xra = *(const float4*)&w3[xch * 128 + 64 + 4 * xk4];
            xrb = *(const float4*)&w3[(xch + 32) * 128 + 64 + 4 * xk4];
        }
        const unsigned aaddr = h2B + (unsigned)(l * H2_S + ti * 64) * 8u;
#pragma unroll
        for (int kk = 0; kk < 64; kk += 2) {
            unsigned long long a0, a1;
            lds_v2(a0, a1, aaddr + kk * 8u);
#pragma unroll
            for (int j = 0; j < 4; j++) {
                unsigned long long w0, w1;
                lds_v2(w0, w1, xrdB + (unsigned)(j * W3_S + kk) * 8u);
                ffma2(C[j], a0, w0);
                ffma2(C[j], a1, w1);
            }
        }
        __syncthreads();
    }
#pragma unroll
    for (int j = 0; j < 4; j++) {
        float e0, e1;
        unpack2(C[j], e0, e1);
        float bi = sm[OFF_BI3 + c2 + j];
        e0 = fmaxf(e0 + bi, 0.f);
        e1 = fmaxf(e1 + bi, 0.f);
        sts_v2(h3B + (unsigned)(l * W3_S + c2 + j) * 8u, e0, e1);
    }
    __syncthreads();

    // ---- stage 3: out = h3 @ W4^T + b4, transposed write ----
    if (t < 128) {
        const int p = t >> 1, c = t & 1;
        const float* h3f = sm + OFF_H3;
        const int pb = (p >> 1) * (2 * W3_S), par = p & 1;
        float a = b4[c];
#pragma unroll
        for (int k = 0; k < 64; k++)
            a += h3f[pb + 2 * k + par] * __ldg(&w4[c * 64 + k]);
        out[(b * NC + c) * NN + n0 + p] = a;
    }
}

// ---------------- launch ----------------
extern "C" void kernel_launch(void* const* d_in, const int* in_sizes, int n_in,
                              void* d_out, int out_size) {
    const float* gl   = (const float*)d_in[0];
    const float* lo   = (const float*)d_in[1];
    const float* cent = (const float*)d_in[2];
    const int*   npc  = (const int*)  d_in[3];
    const float* fc1w = (const float*)d_in[4];
    const float* fc1b = (const float*)d_in[5];
    const float* fc2w = (const float*)d_in[6];
    const float* fc2b = (const float*)d_in[7];
    const float* inw  = (const float*)d_in[8];
    const float* inb  = (const float*)d_in[9];
    const float* ow   = (const float*)d_in[10];
    const float* ob   = (const float*)d_in[11];
    const float* w2   = (const float*)d_in[12];
    const float* cb2  = (const float*)d_in[13];
    const float* gm2  = (const float*)d_in[14];
    const float* bt2  = (const float*)d_in[15];
    const float* mu2  = (const float*)d_in[16];
    const float* va2  = (const float*)d_in[17];
    const float* w3   = (const float*)d_in[18];
    const float* cb3  = (const float*)d_in[19];
    const float* gm3  = (const float*)d_in[20];
    const float* bt3  = (const float*)d_in[21];
    const float* mu3  = (const float*)d_in[22];
    const float* va3  = (const float*)d_in[23];
    const float* w4   = (const float*)d_in[24];
    const float* b4   = (const float*)d_in[25];
    float* out = (float*)d_out;

    const int xqkv_smem = (8320 + 17152) * 4;            // 101,888
    const int attn_smem = (8192 * 2 + 256 * 2 + 8448) * 4; // 101,376
    const int outp_smem = (8320 + 8576) * 4;             // 67,584
    const int mlp_smem  = MLP_FLOATS * 4;                // ~186.6 KB

    cudaFuncSetAttribute(xqkv_kernel,   cudaFuncAttributeMaxDynamicSharedMemorySize, xqkv_smem);
    cudaFuncSetAttribute(attn_kernel,   cudaFuncAttributeMaxDynamicSharedMemorySize, attn_smem);
    cudaFuncSetAttribute(outproj_kernel,cudaFuncAttributeMaxDynamicSharedMemorySize, outp_smem);
    cudaFuncSetAttribute(mlp_kernel,    cudaFuncAttributeMaxDynamicSharedMemorySize, mlp_smem);

    prep_kernel<<<1, 256>>>(npc);
    xk_kernel<<<dim3(S, B), 256>>>(gl, cent, fc1w, fc1b, fc2w, fc2b);
    xqkv_kernel<<<dim3(12, 8, B), 256, xqkv_smem>>>(inw, inb);
    attn_kernel<<<dim3(4, H, B), 256, attn_smem>>>();
    outproj_kernel<<<dim3(8, 8, B), 256, outp_smem>>>(ow, ob);
    mlp_kernel<<<dim3(NN / 64, B), 512, mlp_smem>>>(lo, w2, cb2, gm2, bt2, mu2, va2,
                                                    w3, cb3, gm3, bt3, mu3, va3,
                                                    w4, b4, out);
}

// round 8
// speedup vs baseline: 4.0001x; 2.9870x over previous
#include <cuda_runtime.h>
#include <cuda_bf16.h>
#include <math.h>

#define B 4
#define S 256
#define E 256
#define H 8
#define DH 32
#define LD 128
#define NN 65536
#define NC 2
#define EPS 1e-5f

// ---------------- scratch ----------------
__device__ __align__(16) float g_q[B*H*S*DH];
__device__ __align__(16) float g_k[B*H*S*DH];
__device__ __align__(16) float g_v[B*H*S*DH];
__device__ __align__(16) float g_ctx[B*S*E];
__device__ __align__(16) float g_attn[B*S*E];
__device__ __align__(16) float g_x[B*S*E];
__device__ int g_pref[S + 1];
// W2 folded+split, fragment-major: [chunk6][kstep4][ntile16][lane32] uint2 (b0,b1)
__device__ __align__(16) uint2 g_w2fh[6*4*16*32];
__device__ __align__(16) uint2 g_w2fl[6*4*16*32];
// W3 folded+split, fragment-major: [kstep8][ntile8][lane32]
__device__ __align__(16) uint2 g_w3fh[8*8*32];
__device__ __align__(16) uint2 g_w3fl[8*8*32];
__device__ float g_bi2[128];
__device__ float g_bi3[64];

// ---------------- helpers ----------------
__device__ __forceinline__ unsigned pack_split2(float a0, float a1, unsigned &lo2) {
    __nv_bfloat16 h0 = __float2bfloat16(a0);
    __nv_bfloat16 h1 = __float2bfloat16(a1);
    float r0 = __bfloat162float(h0), r1 = __bfloat162float(h1);
    __nv_bfloat16 l0 = __float2bfloat16(a0 - r0);
    __nv_bfloat16 l1 = __float2bfloat16(a1 - r1);
    lo2 = ((unsigned)__bfloat16_as_ushort(l1) << 16) | (unsigned)__bfloat16_as_ushort(l0);
    return ((unsigned)__bfloat16_as_ushort(h1) << 16) | (unsigned)__bfloat16_as_ushort(h0);
}
__device__ __forceinline__ void sts64(unsigned a, unsigned x, unsigned y) {
    asm volatile("st.shared.v2.b32 [%0],{%1,%2};" :: "r"(a), "r"(x), "r"(y) : "memory");
}
__device__ __forceinline__ void ldmx4(unsigned* r, unsigned addr) {
    asm volatile("ldmatrix.sync.aligned.m8n8.x4.shared.b16 {%0,%1,%2,%3},[%4];"
                 : "=r"(r[0]), "=r"(r[1]), "=r"(r[2]), "=r"(r[3]) : "r"(addr));
}
__device__ __forceinline__ void mma_bf16(float &d0, float &d1, float &d2, float &d3,
                                         const unsigned* a, unsigned b0, unsigned b1) {
    asm volatile("mma.sync.aligned.m16n8k16.row.col.f32.bf16.bf16.f32 "
                 "{%0,%1,%2,%3},{%4,%5,%6,%7},{%8,%9},{%0,%1,%2,%3};"
                 : "+f"(d0), "+f"(d1), "+f"(d2), "+f"(d3)
                 : "r"(a[0]), "r"(a[1]), "r"(a[2]), "r"(a[3]), "r"(b0), "r"(b1));
}

// ---------------- kernel 1: prefix sums ----------------
__global__ void prep_kernel(const int* __restrict__ npc) {
    __shared__ int vals[S];
    int t = threadIdx.x;
    vals[t] = npc[t];
    __syncthreads();
    if (t == 0) {
        int a = 0;
        for (int s = 0; s < S; s++) { g_pref[s] = a; a += vals[s]; }
        g_pref[S] = a;
    }
}

// ---------------- kernel 1b: W2 -> folded/split fragment-major ----------------
__global__ void wfrag2_kernel(const float* __restrict__ w2, const float* __restrict__ cb2,
                              const float* __restrict__ gm2, const float* __restrict__ bt2,
                              const float* __restrict__ mu2, const float* __restrict__ va2) {
    int id = blockIdx.x * 256 + threadIdx.x;
    if (id >= 6*4*16*32) return;
    int lane = id & 31;
    int nt = (id >> 5) & 15;
    int ks = (id >> 9) & 3;
    int ch = id >> 11;                 // chunk 0-5
    int n = nt * 8 + (lane >> 2);
    int k0 = ch * 64 + ks * 16 + 2 * (lane & 3);
    float s = gm2[n] * rsqrtf(va2[n] + EPS);
    if (ch == 0 && ks == 0 && (lane & 3) == 0)
        g_bi2[n] = (cb2[n] - mu2[n]) * s + bt2[n];
    float v0 = w2[n * 384 + k0] * s,     v1 = w2[n * 384 + k0 + 1] * s;
    float v2 = w2[n * 384 + k0 + 8] * s, v3 = w2[n * 384 + k0 + 9] * s;
    unsigned l0, l1;
    unsigned h0 = pack_split2(v0, v1, l0);
    unsigned h1 = pack_split2(v2, v3, l1);
    g_w2fh[id] = make_uint2(h0, h1);
    g_w2fl[id] = make_uint2(l0, l1);
}

// ---------------- kernel 1c: W3 -> folded/split fragment-major ----------------
__global__ void wfrag3_kernel(const float* __restrict__ w3, const float* __restrict__ cb3,
                              const float* __restrict__ gm3, const float* __restrict__ bt3,
                              const float* __restrict__ mu3, const float* __restrict__ va3) {
    int id = blockIdx.x * 256 + threadIdx.x;
    if (id >= 8*8*32) return;
    int lane = id & 31;
    int nt = (id >> 5) & 7;
    int ks = id >> 8;                  // 0-7
    int n = nt * 8 + (lane >> 2);
    int k0 = ks * 16 + 2 * (lane & 3);
    float s = gm3[n] * rsqrtf(va3[n] + EPS);
    if (ks == 0 && (lane & 3) == 0)
        g_bi3[n] = (cb3[n] - mu3[n]) * s + bt3[n];
    float v0 = w3[n * 128 + k0] * s,     v1 = w3[n * 128 + k0 + 1] * s;
    float v2 = w3[n * 128 + k0 + 8] * s, v3 = w3[n * 128 + k0 + 9] * s;
    unsigned l0, l1;
    unsigned h0 = pack_split2(v0, v1, l0);
    unsigned h1 = pack_split2(v2, v3, l1);
    g_w3fh[id] = make_uint2(h0, h1);
    g_w3fl[id] = make_uint2(l0, l1);
}

// ---------------- kernel 2: x = gl^T + pos(centroids) ----------------
__global__ void xk_kernel(const float* __restrict__ gl, const float* __restrict__ cent,
                          const float* __restrict__ fc1w, const float* __restrict__ fc1b,
                          const float* __restrict__ fc2w, const float* __restrict__ fc2b) {
    const int s = blockIdx.x, b = blockIdx.y, e = threadIdx.x;
    const float c0 = cent[(b * S + s) * 2 + 0];
    const float c1 = cent[(b * S + s) * 2 + 1];
    float pos = fc2b[e];
#pragma unroll
    for (int j = 0; j < 16; j++) {
        float hh = fc1b[j] + c0 * fc1w[2 * j] + c1 * fc1w[2 * j + 1];
        hh = (hh >= 0.f) ? hh : 0.01f * hh;
        pos += hh * fc2w[e * 16 + j];
    }
    g_x[(b * S + s) * E + e] = gl[(s * B + b) * E + e] + pos;
}

// ---------------- kernel 3: qkv ----------------
__global__ void xqkv_kernel(const float* __restrict__ inw, const float* __restrict__ inb) {
    extern __shared__ float sh[];
    float* xs = sh;
    float* ws = sh + 8320;
    const int t = threadIdx.x;
    const int chunk = blockIdx.x, stile = blockIdx.y, b = blockIdx.z;
    const int s0 = stile * 32;
    for (int p = 0; p < 8; p++) {
        int i4 = t + p * 256;
        int s = i4 >> 6, e4 = i4 & 63;
        *(float4*)&xs[s * 260 + 4 * e4] = *(const float4*)&g_x[(b * S + s0 + s) * E + 4 * e4];
    }
    for (int p = 0; p < 16; p++) {
        int i4 = t + p * 256;
        int o = i4 >> 6, k4 = i4 & 63;
        *(float4*)&ws[o * 268 + 4 * k4] = *(const float4*)&inw[(chunk * 64 + o) * 256 + 4 * k4];
    }
    __syncthreads();
    const int ol = t & 63, sb = (t >> 6) * 8;
    float acc[8];
#pragma unroll
    for (int i = 0; i < 8; i++) acc[i] = 0.f;
#pragma unroll 8
    for (int k4 = 0; k4 < 64; k4++) {
        float4 wv = *(float4*)&ws[ol * 268 + 4 * k4];
#pragma unroll
        for (int i = 0; i < 8; i++) {
            float4 av = *(float4*)&xs[(sb + i) * 260 + 4 * k4];
            acc[i] += wv.x * av.x + wv.y * av.y + wv.z * av.z + wv.w * av.w;
        }
    }
    const int og = chunk * 64 + ol;
    const float bb = inb[og];
    const int part = og >> 8, e = og & 255, hh = e >> 5, d = e & 31;
    float* dst = (part == 0) ? g_q : ((part == 1) ? g_k : g_v);
#pragma unroll
    for (int i = 0; i < 8; i++) {
        int s = s0 + sb + i;
        dst[((b * H + hh) * S + s) * DH + d] = acc[i] + bb;
    }
}

// ---------------- kernel 4: attention ----------------
__global__ void attn_kernel() {
    extern __shared__ float sh[];
    float* ks  = sh;
    float* vs  = sh + 8192;
    float* pm  = vs + 8192;
    float* pl  = pm + 256;
    float* pac = pl + 256;
    const int t = threadIdx.x;
    const int b = blockIdx.z, h = blockIdx.y;
    const int base = ((b * H + h) * S) * DH;
    for (int i = t; i < 2048; i += 256) {
        ((float4*)ks)[i] = ((const float4*)(g_k + base))[i];
        ((float4*)vs)[i] = ((const float4*)(g_v + base))[i];
    }
    __syncthreads();
    const int q = t & 63, jh = t >> 6;
    const int qg = blockIdx.x * 64 + q;
    float qr[DH];
#pragma unroll
    for (int i = 0; i < 8; i++) ((float4*)qr)[i] = ((const float4*)(g_q + base + qg * DH))[i];
    const float scale = 0.17677669529663687f;
    float m = -1e30f, l = 0.f, acc[DH];
#pragma unroll
    for (int d = 0; d < DH; d++) acc[d] = 0.f;
    for (int j = jh * 64; j < jh * 64 + 64; j++) {
        float sc = 0.f;
#pragma unroll
        for (int d = 0; d < DH; d++) sc += qr[d] * ks[j * DH + d];
        sc *= scale;
        float mn = fmaxf(m, sc);
        float corr = __expf(m - mn);
        float p = __expf(sc - mn);
        m = mn;
        l = l * corr + p;
#pragma unroll
        for (int d = 0; d < DH; d++) acc[d] = acc[d] * corr + p * vs[j * DH + d];
    }
    pm[jh * 64 + q] = m;
    pl[jh * 64 + q] = l;
#pragma unroll
    for (int d = 0; d < DH; d++) pac[(jh * 64 + q) * 33 + d] = acc[d];
    __syncthreads();
    if (t < 64) {
        float M = pm[t];
#pragma unroll
        for (int i = 1; i < 4; i++) M = fmaxf(M, pm[i * 64 + t]);
        float e0 = __expf(pm[t] - M), e1 = __expf(pm[64 + t] - M),
              e2 = __expf(pm[128 + t] - M), e3 = __expf(pm[192 + t] - M);
        float L = pl[t] * e0 + pl[64 + t] * e1 + pl[128 + t] * e2 + pl[192 + t] * e3;
        float inv = 1.f / L;
        int qo = blockIdx.x * 64 + t;
#pragma unroll
        for (int d = 0; d < DH; d++) {
            float v = pac[t * 33 + d] * e0 + pac[(64 + t) * 33 + d] * e1 +
                      pac[(128 + t) * 33 + d] * e2 + pac[(192 + t) * 33 + d] * e3;
            g_ctx[(b * S + qo) * E + h * DH + d] = v * inv;
        }
    }
}

// ---------------- kernel 5: out_proj ----------------
__global__ void outproj_kernel(const float* __restrict__ ow, const float* __restrict__ ob) {
    extern __shared__ float sh[];
    float* cs = sh;
    float* ws = sh + 8320;
    const int t = threadIdx.x;
    const int chunk = blockIdx.x, stile = blockIdx.y, b = blockIdx.z;
    const int s0 = stile * 32;
    for (int p = 0; p < 8; p++) {
        int i4 = t + p * 256;
        int s = i4 >> 6, e4 = i4 & 63;
        *(float4*)&cs[s * 260 + 4 * e4] = *(const float4*)&g_ctx[(b * S + s0 + s) * E + 4 * e4];
    }
    for (int p = 0; p < 8; p++) {
        int i4 = t + p * 256;
        int o = i4 >> 6, k4 = i4 & 63;
        *(float4*)&ws[o * 268 + 4 * k4] = *(const float4*)&ow[(chunk * 32 + o) * 256 + 4 * k4];
    }
    __syncthreads();
    const int ol = t & 31, sb = (t >> 5) * 4;
    float acc[4] = {0.f, 0.f, 0.f, 0.f};
#pragma unroll 8
    for (int k4 = 0; k4 < 64; k4++) {
        float4 wv = *(float4*)&ws[ol * 268 + 4 * k4];
#pragma unroll
        for (int i = 0; i < 4; i++) {
            float4 av = *(float4*)&cs[(sb + i) * 260 + 4 * k4];
            acc[i] += wv.x * av.x + wv.y * av.y + wv.z * av.z + wv.w * av.w;
        }
    }
    const int og = chunk * 32 + ol;
    const float bb = ob[og];
#pragma unroll
    for (int i = 0; i < 4; i++)
        g_attn[(b * S + s0 + sb + i) * E + og] = acc[i] + bb;
}

// ---------------- kernel 6: mma.sync point-MLP ----------------
// A buffers: 2 x (hi+lo) x [128 rows][72 bf16] stride 144B.
#define AB0H 0
#define AB0L 18432
#define AB1H 36864
#define AB1L 55296
#define ABUF(i, v) ((i) ? ((v) ? AB1L : AB1H) : ((v) ? AB0L : AB0H))
#define MT_H3   73728                 // 128*66*4 = 33792
#define MT_BI2  107520                // 512
#define MT_BI3  108032                // 256
#define MT_W4S  108288                // 512
#define MT_PREF 108800                // 1028
#define MT_CID  109856                // 512
#define MT_SIZE 110592

__global__ __launch_bounds__(256)
void mlp_mma_kernel(const float* __restrict__ lo, const float* __restrict__ w4,
                    const float* __restrict__ b4, float* __restrict__ out) {
    extern __shared__ __align__(16) char smc[];
    float* h3f  = (float*)(smc + MT_H3);
    float* bi2s = (float*)(smc + MT_BI2);
    float* bi3s = (float*)(smc + MT_BI3);
    float* w4s  = (float*)(smc + MT_W4S);
    int*   pref = (int*)(smc + MT_PREF);
    int*   cid  = (int*)(smc + MT_CID);
    const unsigned smemB = (unsigned)__cvta_generic_to_shared(smc);

    const int t = threadIdx.x;
    const int w = t >> 5, lane = t & 31;
    const int b = blockIdx.y;
    const int n0 = blockIdx.x * 128;

    if (t < 128) { bi2s[t] = g_bi2[t]; w4s[t] = w4[t]; }
    if (t >= 128 && t < 192) bi3s[t - 128] = g_bi3[t - 128];
    if (t < 257) pref[t] = g_pref[t];
    __syncthreads();
    if (t < 128) {
        int i = n0 + t;
        int s = 0;
#pragma unroll
        for (int step = 128; step >= 1; step >>= 1)
            if (s + step <= 255 && pref[s + step] <= i) s += step;
        cid[t] = s;
    }
    __syncthreads();

    // gather thread mapping: row = t>>1 (0-127), kh = (t&1)*32
    const int grow = t >> 1, gkh = (t & 1) * 32;

    // ldmatrix lane address components
    const int arow = (lane & 7) + ((lane >> 3) & 1) * 8;   // row within 16
    const int akb  = (lane >> 4) * 16;                      // k-byte offset within 32B

    // warp tiling stage1: 64 pts x 32 ch
    const int wm = w >> 2, wn = w & 3;

    float acc[4][4][4];
#pragma unroll
    for (int mt = 0; mt < 4; mt++)
#pragma unroll
        for (int nt = 0; nt < 4; nt++)
#pragma unroll
            for (int r = 0; r < 4; r++) acc[mt][nt][r] = 0.f;

    // ---- gather chunk 0 ----
    {
        const float* src = lo + ((size_t)(b * NN + n0 + grow)) * LD + gkh;
        unsigned hb = smemB + ABUF(0, 0) + grow * 144 + gkh * 2;
        unsigned lb = smemB + ABUF(0, 1) + grow * 144 + gkh * 2;
#pragma unroll
        for (int j = 0; j < 8; j++) {
            float4 v = *(const float4*)(src + 4 * j);
            unsigned l0, l1;
            unsigned h0 = pack_split2(v.x, v.y, l0);
            unsigned h1 = pack_split2(v.z, v.w, l1);
            sts64(hb + 8 * j, h0, h1);
            sts64(lb + 8 * j, l0, l1);
        }
    }
    __syncthreads();

    // ---- stage 1: 6 chunks of K=64 ----
    for (int c = 0; c < 6; c++) {
        const int buf = c & 1;
        const unsigned ah = smemB + ABUF(buf, 0);
        const unsigned al = smemB + ABUF(buf, 1);
#pragma unroll
        for (int ks = 0; ks < 4; ks++) {
            // B fragments (direct from gmem, fragment-major)
            uint2 bh[4], bl[4];
#pragma unroll
            for (int nt = 0; nt < 4; nt++) {
                int idx = ((c * 4 + ks) * 16 + wn * 4 + nt) * 32 + lane;
                bh[nt] = __ldg(&g_w2fh[idx]);
                bl[nt] = __ldg(&g_w2fl[idx]);
            }
#pragma unroll
            for (int mt = 0; mt < 4; mt++) {
                unsigned base = (wm * 64 + mt * 16 + arow) * 144 + ks * 32 + akb;
                unsigned fah[4], fal[4];
                ldmx4(fah, ah + base);
                ldmx4(fal, al + base);
#pragma unroll
                for (int nt = 0; nt < 4; nt++) {
                    mma_bf16(acc[mt][nt][0], acc[mt][nt][1], acc[mt][nt][2], acc[mt][nt][3],
                             fah, bh[nt].x, bh[nt].y);
                    mma_bf16(acc[mt][nt][0], acc[mt][nt][1], acc[mt][nt][2], acc[mt][nt][3],
                             fah, bl[nt].x, bl[nt].y);
                    mma_bf16(acc[mt][nt][0], acc[mt][nt][1], acc[mt][nt][2], acc[mt][nt][3],
                             fal, bh[nt].x, bh[nt].y);
                }
            }
        }
        // gather next chunk into the other buffer
        if (c < 5) {
            const int nc = c + 1;
            const float* src = (nc < 2)
                ? (lo + ((size_t)(b * NN + n0 + grow)) * LD + nc * 64 + gkh)
                : (g_attn + ((size_t)(b * S + cid[grow])) * E + (nc - 2) * 64 + gkh);
            unsigned hb = smemB + ABUF(nc & 1, 0) + grow * 144 + gkh * 2;
            unsigned lb = smemB + ABUF(nc & 1, 1) + grow * 144 + gkh * 2;
#pragma unroll
            for (int j = 0; j < 8; j++) {
                float4 v = *(const float4*)(src + 4 * j);
                unsigned l0, l1;
                unsigned h0 = pack_split2(v.x, v.y, l0);
                unsigned h1 = pack_split2(v.z, v.w, l1);
                sts64(hb + 8 * j, h0, h1);
                sts64(lb + 8 * j, l0, l1);
            }
        }
        __syncthreads();
    }

    // ---- stage1 epilogue: bias + relu + split -> A2 buffers (ch 0-63 -> buf0, 64-127 -> buf1) ----
    {
        const int g = lane >> 2, tg = lane & 3;
#pragma unroll
        for (int mt = 0; mt < 4; mt++) {
#pragma unroll
            for (int nt = 0; nt < 4; nt++) {
                int col = wn * 32 + nt * 8 + 2 * tg;
                int bufi = col >> 6;
                unsigned off = (col & 63) * 2;
                float bia = bi2s[col], bib = bi2s[col + 1];
                int r0 = wm * 64 + mt * 16 + g;
                float v0 = fmaxf(acc[mt][nt][0] + bia, 0.f);
                float v1 = fmaxf(acc[mt][nt][1] + bib, 0.f);
                unsigned lw;
                unsigned hw = pack_split2(v0, v1, lw);
                *(unsigned*)(smc + ABUF(bufi, 0) + r0 * 144 + off) = hw;
                *(unsigned*)(smc + ABUF(bufi, 1) + r0 * 144 + off) = lw;
                int r1 = r0 + 8;
                float v2 = fmaxf(acc[mt][nt][2] + bia, 0.f);
                float v3 = fmaxf(acc[mt][nt][3] + bib, 0.f);
                unsigned hw2 = pack_split2(v2, v3, lw);
                *(unsigned*)(smc + ABUF(bufi, 0) + r1 * 144 + off) = hw2;
                *(unsigned*)(smc + ABUF(bufi, 1) + r1 * 144 + off) = lw;
            }
        }
    }
    __syncthreads();

    // ---- stage 2: K=128 (8 ksteps), warp tile 32 pts x 32 ch ----
    const int wm2 = w >> 1, wn2 = w & 1;
    float ac2[2][4][4];
#pragma unroll
    for (int mt = 0; mt < 2; mt++)
#pragma unroll
        for (int nt = 0; nt < 4; nt++)
#pragma unroll
            for (int r = 0; r < 4; r++) ac2[mt][nt][r] = 0.f;

#pragma unroll
    for (int ks = 0; ks < 8; ks++) {
        const int bufi = ks >> 2, ki = ks & 3;
        const unsigned ah = smemB + ABUF(bufi, 0);
        const unsigned al = smemB + ABUF(bufi, 1);
        uint2 bh[4], bl[4];
#pragma unroll
        for (int nt = 0; nt < 4; nt++) {
            int idx = (ks * 8 + wn2 * 4 + nt) * 32 + lane;
            bh[nt] = __ldg(&g_w3fh[idx]);
            bl[nt] = __ldg(&g_w3fl[idx]);
        }
#pragma unroll
        for (int mt = 0; mt < 2; mt++) {
            unsigned base = (wm2 * 32 + mt * 16 + arow) * 144 + ki * 32 + akb;
            unsigned fah[4], fal[4];
            ldmx4(fah, ah + base);
            ldmx4(fal, al + base);
#pragma unroll
            for (int nt = 0; nt < 4; nt++) {
                mma_bf16(ac2[mt][nt][0], ac2[mt][nt][1], ac2[mt][nt][2], ac2[mt][nt][3],
                         fah, bh[nt].x, bh[nt].y);
                mma_bf16(ac2[mt][nt][0], ac2[mt][nt][1], ac2[mt][nt][2], ac2[mt][nt][3],
                         fah, bl[nt].x, bl[nt].y);
                mma_bf16(ac2[mt][nt][0], ac2[mt][nt][1], ac2[mt][nt][2], ac2[mt][nt][3],
                         fal, bh[nt].x, bh[nt].y);
            }
        }
    }

    // ---- stage2 epilogue: h3 fp32 into smem ----
    {
        const int g = lane >> 2, tg = lane & 3;
#pragma unroll
        for (int mt = 0; mt < 2; mt++) {
#pragma unroll
            for (int nt = 0; nt < 4; nt++) {
                int col = wn2 * 32 + nt * 8 + 2 * tg;
                float bia = bi3s[col], bib = bi3s[col + 1];
                int r0 = wm2 * 32 + mt * 16 + g;
                h3f[r0 * 66 + col]     = fmaxf(ac2[mt][nt][0] + bia, 0.f);
                h3f[r0 * 66 + col + 1] = fmaxf(ac2[mt][nt][1] + bib, 0.f);
                int r1 = r0 + 8;
                h3f[r1 * 66 + col]     = fmaxf(ac2[mt][nt][2] + bia, 0.f);
                h3f[r1 * 66 + col + 1] = fmaxf(ac2[mt][nt][3] + bib, 0.f);
            }
        }
    }
    __syncthreads();

    // ---- conv4 + transposed write ----
    if (t < 128) {
        const int p = t;
        float a0 = b4[0], a1 = b4[1];
#pragma unroll
        for (int k = 0; k < 64; k++) {
            float v = h3f[p * 66 + k];
            a0 += v * w4s[k];
            a1 += v * w4s[64 + k];
        }
        out[(size_t)(b * NC + 0) * NN + n0 + p] = a0;
        out[(size_t)(b * NC + 1) * NN + n0 + p] = a1;
    }
}

// ---------------- launch ----------------
extern "C" void kernel_launch(void* const* d_in, const int* in_sizes, int n_in,
                              void* d_out, int out_size) {
    const float* gl   = (const float*)d_in[0];
    const float* lo   = (const float*)d_in[1];
    const float* cent = (const float*)d_in[2];
    const int*   npc  = (const int*)  d_in[3];
    const float* fc1w = (const float*)d_in[4];
    const float* fc1b = (const float*)d_in[5];
    const float* fc2w = (const float*)d_in[6];
    const float* fc2b = (const float*)d_in[7];
    const float* inw  = (const float*)d_in[8];
    const float* inb  = (const float*)d_in[9];
    const float* ow   = (const float*)d_in[10];
    const float* ob   = (const float*)d_in[11];
    const float* w2   = (const float*)d_in[12];
    const float* cb2  = (const float*)d_in[13];
    const float* gm2  = (const float*)d_in[14];
    const float* bt2  = (const float*)d_in[15];
    const float* mu2  = (const float*)d_in[16];
    const float* va2  = (const float*)d_in[17];
    const float* w3   = (const float*)d_in[18];
    const float* cb3  = (const float*)d_in[19];
    const float* gm3  = (const float*)d_in[20];
    const float* bt3  = (const float*)d_in[21];
    const float* mu3  = (const float*)d_in[22];
    const float* va3  = (const float*)d_in[23];
    const float* w4   = (const float*)d_in[24];
    const float* b4   = (const float*)d_in[25];
    float* out = (float*)d_out;

    const int xqkv_smem = (8320 + 17152) * 4;
    const int attn_smem = (8192 * 2 + 256 * 2 + 8448) * 4;
    const int outp_smem = (8320 + 8576) * 4;

    cudaFuncSetAttribute(xqkv_kernel,    cudaFuncAttributeMaxDynamicSharedMemorySize, xqkv_smem);
    cudaFuncSetAttribute(attn_kernel,    cudaFuncAttributeMaxDynamicSharedMemorySize, attn_smem);
    cudaFuncSetAttribute(outproj_kernel, cudaFuncAttributeMaxDynamicSharedMemorySize, outp_smem);
    cudaFuncSetAttribute(mlp_mma_kernel, cudaFuncAttributeMaxDynamicSharedMemorySize, MT_SIZE);

    prep_kernel<<<1, 256>>>(npc);
    wfrag2_kernel<<<48, 256>>>(w2, cb2, gm2, bt2, mu2, va2);
    wfrag3_kernel<<<8, 256>>>(w3, cb3, gm3, bt3, mu3, va3);
    xk_kernel<<<dim3(S, B), 256>>>(gl, cent, fc1w, fc1b, fc2w, fc2b);
    xqkv_kernel<<<dim3(12, 8, B), 256, xqkv_smem>>>(inw, inb);
    attn_kernel<<<dim3(4, H, B), 256, attn_smem>>>();
    outproj_kernel<<<dim3(8, 8, B), 256, outp_smem>>>(ow, ob);
    mlp_mma_kernel<<<dim3(NN / 128, B), 256, MT_SIZE>>>(lo, w4, b4, out);
}

// round 9
// speedup vs baseline: 5.1410x; 1.2852x over previous
#include <cuda_runtime.h>
#include <cuda_fp16.h>
#include <math.h>

#define B 4
#define S 256
#define E 256
#define H 8
#define DH 32
#define LD 128
#define NN 65536
#define NC 2
#define EPS 1e-5f

// ---------------- scratch ----------------
__device__ __align__(16) float g_q[B*H*S*DH];
__device__ __align__(16) float g_k[B*H*S*DH];
__device__ __align__(16) float g_v[B*H*S*DH];
__device__ __align__(16) float g_ctx[B*S*E];
__device__ __align__(16) float g_attn[B*S*E];
__device__ __align__(16) float g_x[B*S*E];
__device__ int g_pref[S + 1];
// W2 folded+split fp16, fragment-major: [chunk6][kstep4][ntile16][lane32] uint2
__device__ __align__(16) uint2 g_w2fh[6*4*16*32];
__device__ __align__(16) uint2 g_w2fl[6*4*16*32];
// W3 folded+split fp16, fragment-major: [kstep8][ntile8][lane32]
__device__ __align__(16) uint2 g_w3fh[8*8*32];
__device__ __align__(16) uint2 g_w3fl[8*8*32];
__device__ float g_bi2[128];
__device__ float g_bi3[64];

// ---------------- helpers ----------------
__device__ __forceinline__ unsigned pack2h(float a0, float a1) {
    __half2 h = __floats2half2_rn(a0, a1);
    return *reinterpret_cast<unsigned*>(&h);
}
__device__ __forceinline__ unsigned pack_split2h(float a0, float a1, unsigned &lo2) {
    __half h0 = __float2half_rn(a0), h1 = __float2half_rn(a1);
    __half l0 = __float2half_rn(a0 - __half2float(h0));
    __half l1 = __float2half_rn(a1 - __half2float(h1));
    lo2 = ((unsigned)__half_as_ushort(l1) << 16) | (unsigned)__half_as_ushort(l0);
    return ((unsigned)__half_as_ushort(h1) << 16) | (unsigned)__half_as_ushort(h0);
}
__device__ __forceinline__ void sts64(unsigned a, unsigned x, unsigned y) {
    asm volatile("st.shared.v2.b32 [%0],{%1,%2};" :: "r"(a), "r"(x), "r"(y) : "memory");
}
__device__ __forceinline__ void ldmx4(unsigned* r, unsigned addr) {
    asm volatile("ldmatrix.sync.aligned.m8n8.x4.shared.b16 {%0,%1,%2,%3},[%4];"
                 : "=r"(r[0]), "=r"(r[1]), "=r"(r[2]), "=r"(r[3]) : "r"(addr));
}
__device__ __forceinline__ void mma_f16(float &d0, float &d1, float &d2, float &d3,
                                        const unsigned* a, unsigned b0, unsigned b1) {
    asm volatile("mma.sync.aligned.m16n8k16.row.col.f32.f16.f16.f32 "
                 "{%0,%1,%2,%3},{%4,%5,%6,%7},{%8,%9},{%0,%1,%2,%3};"
                 : "+f"(d0), "+f"(d1), "+f"(d2), "+f"(d3)
                 : "r"(a[0]), "r"(a[1]), "r"(a[2]), "r"(a[3]), "r"(b0), "r"(b1));
}

// ---------------- kernel 1: prefix sums ----------------
__global__ void prep_kernel(const int* __restrict__ npc) {
    __shared__ int vals[S];
    int t = threadIdx.x;
    vals[t] = npc[t];
    __syncthreads();
    if (t == 0) {
        int a = 0;
        for (int s = 0; s < S; s++) { g_pref[s] = a; a += vals[s]; }
        g_pref[S] = a;
    }
}

// ---------------- kernel 1b: W2 -> folded/split fp16 fragment-major ----------------
__global__ void wfrag2_kernel(const float* __restrict__ w2, const float* __restrict__ cb2,
                              const float* __restrict__ gm2, const float* __restrict__ bt2,
                              const float* __restrict__ mu2, const float* __restrict__ va2) {
    int id = blockIdx.x * 256 + threadIdx.x;
    if (id >= 6*4*16*32) return;
    int lane = id & 31;
    int nt = (id >> 5) & 15;
    int ks = (id >> 9) & 3;
    int ch = id >> 11;
    int n = nt * 8 + (lane >> 2);
    int k0 = ch * 64 + ks * 16 + 2 * (lane & 3);
    float s = gm2[n] * rsqrtf(va2[n] + EPS);
    if (ch == 0 && ks == 0 && (lane & 3) == 0)
        g_bi2[n] = (cb2[n] - mu2[n]) * s + bt2[n];
    float v0 = w2[n * 384 + k0] * s,     v1 = w2[n * 384 + k0 + 1] * s;
    float v2 = w2[n * 384 + k0 + 8] * s, v3 = w2[n * 384 + k0 + 9] * s;
    unsigned l0, l1;
    unsigned h0 = pack_split2h(v0, v1, l0);
    unsigned h1 = pack_split2h(v2, v3, l1);
    g_w2fh[id] = make_uint2(h0, h1);
    g_w2fl[id] = make_uint2(l0, l1);
}

// ---------------- kernel 1c: W3 -> folded/split fp16 fragment-major ----------------
__global__ void wfrag3_kernel(const float* __restrict__ w3, const float* __restrict__ cb3,
                              const float* __restrict__ gm3, const float* __restrict__ bt3,
                              const float* __restrict__ mu3, const float* __restrict__ va3) {
    int id = blockIdx.x * 256 + threadIdx.x;
    if (id >= 8*8*32) return;
    int lane = id & 31;
    int nt = (id >> 5) & 7;
    int ks = id >> 8;
    int n = nt * 8 + (lane >> 2);
    int k0 = ks * 16 + 2 * (lane & 3);
    float s = gm3[n] * rsqrtf(va3[n] + EPS);
    if (ks == 0 && (lane & 3) == 0)
        g_bi3[n] = (cb3[n] - mu3[n]) * s + bt3[n];
    float v0 = w3[n * 128 + k0] * s,     v1 = w3[n * 128 + k0 + 1] * s;
    float v2 = w3[n * 128 + k0 + 8] * s, v3 = w3[n * 128 + k0 + 9] * s;
    unsigned l0, l1;
    unsigned h0 = pack_split2h(v0, v1, l0);
    unsigned h1 = pack_split2h(v2, v3, l1);
    g_w3fh[id] = make_uint2(h0, h1);
    g_w3fl[id] = make_uint2(l0, l1);
}

// ---------------- kernel 2: x = gl^T + pos(centroids), grid (8,B) x 256 ----------------
__global__ void xk_kernel(const float* __restrict__ gl, const float* __restrict__ cent,
                          const float* __restrict__ fc1w, const float* __restrict__ fc1b,
                          const float* __restrict__ fc2w, const float* __restrict__ fc2b) {
    const int b = blockIdx.y, s0 = blockIdx.x * 32, e = threadIdx.x;
    float w2r[16];
#pragma unroll
    for (int j = 0; j < 16; j++) w2r[j] = fc2w[e * 16 + j];
    const float fb = fc2b[e];
    for (int sr = 0; sr < 32; sr++) {
        int s = s0 + sr;
        float c0 = cent[(b * S + s) * 2 + 0];
        float c1 = cent[(b * S + s) * 2 + 1];
        float pos = fb;
#pragma unroll
        for (int j = 0; j < 16; j++) {
            float hh = fc1b[j] + c0 * fc1w[2 * j] + c1 * fc1w[2 * j + 1];
            hh = (hh >= 0.f) ? hh : 0.01f * hh;
            pos += hh * w2r[j];
        }
        g_x[(b * S + s) * E + e] = gl[(s * B + b) * E + e] + pos;
    }
}

// ---------------- kernel 3: qkv ----------------
__global__ void xqkv_kernel(const float* __restrict__ inw, const float* __restrict__ inb) {
    extern __shared__ float sh[];
    float* xs = sh;
    float* ws = sh + 8320;
    const int t = threadIdx.x;
    const int chunk = blockIdx.x, stile = blockIdx.y, b = blockIdx.z;
    const int s0 = stile * 32;
    for (int p = 0; p < 8; p++) {
        int i4 = t + p * 256;
        int s = i4 >> 6, e4 = i4 & 63;
        *(float4*)&xs[s * 260 + 4 * e4] = *(const float4*)&g_x[(b * S + s0 + s) * E + 4 * e4];
    }
    for (int p = 0; p < 16; p++) {
        int i4 = t + p * 256;
        int o = i4 >> 6, k4 = i4 & 63;
        *(float4*)&ws[o * 268 + 4 * k4] = *(const float4*)&inw[(chunk * 64 + o) * 256 + 4 * k4];
    }
    __syncthreads();
    const int ol = t & 63, sb = (t >> 6) * 8;
    float acc[8];
#pragma unroll
    for (int i = 0; i < 8; i++) acc[i] = 0.f;
#pragma unroll 8
    for (int k4 = 0; k4 < 64; k4++) {
        float4 wv = *(float4*)&ws[ol * 268 + 4 * k4];
#pragma unroll
        for (int i = 0; i < 8; i++) {
            float4 av = *(float4*)&xs[(sb + i) * 260 + 4 * k4];
            acc[i] += wv.x * av.x + wv.y * av.y + wv.z * av.z + wv.w * av.w;
        }
    }
    const int og = chunk * 64 + ol;
    const float bb = inb[og];
    const int part = og >> 8, e = og & 255, hh = e >> 5, d = e & 31;
    float* dst = (part == 0) ? g_q : ((part == 1) ? g_k : g_v);
#pragma unroll
    for (int i = 0; i < 8; i++) {
        int s = s0 + sb + i;
        dst[((b * H + hh) * S + s) * DH + d] = acc[i] + bb;
    }
}

// ---------------- kernel 4: attention ----------------
__global__ void attn_kernel() {
    extern __shared__ float sh[];
    float* ks  = sh;
    float* vs  = sh + 8192;
    float* pm  = vs + 8192;
    float* pl  = pm + 256;
    float* pac = pl + 256;
    const int t = threadIdx.x;
    const int b = blockIdx.z, h = blockIdx.y;
    const int base = ((b * H + h) * S) * DH;
    for (int i = t; i < 2048; i += 256) {
        ((float4*)ks)[i] = ((const float4*)(g_k + base))[i];
        ((float4*)vs)[i] = ((const float4*)(g_v + base))[i];
    }
    __syncthreads();
    const int q = t & 63, jh = t >> 6;
    const int qg = blockIdx.x * 64 + q;
    float qr[DH];
#pragma unroll
    for (int i = 0; i < 8; i++) ((float4*)qr)[i] = ((const float4*)(g_q + base + qg * DH))[i];
    const float scale = 0.17677669529663687f;
    float m = -1e30f, l = 0.f, acc[DH];
#pragma unroll
    for (int d = 0; d < DH; d++) acc[d] = 0.f;
    for (int j = jh * 64; j < jh * 64 + 64; j++) {
        float sc = 0.f;
#pragma unroll
        for (int d = 0; d < DH; d++) sc += qr[d] * ks[j * DH + d];
        sc *= scale;
        float mn = fmaxf(m, sc);
        float corr = __expf(m - mn);
        float p = __expf(sc - mn);
        m = mn;
        l = l * corr + p;
#pragma unroll
        for (int d = 0; d < DH; d++) acc[d] = acc[d] * corr + p * vs[j * DH + d];
    }
    pm[jh * 64 + q] = m;
    pl[jh * 64 + q] = l;
#pragma unroll
    for (int d = 0; d < DH; d++) pac[(jh * 64 + q) * 33 + d] = acc[d];
    __syncthreads();
    if (t < 64) {
        float M = pm[t];
#pragma unroll
        for (int i = 1; i < 4; i++) M = fmaxf(M, pm[i * 64 + t]);
        float e0 = __expf(pm[t] - M), e1 = __expf(pm[64 + t] - M),
              e2 = __expf(pm[128 + t] - M), e3 = __expf(pm[192 + t] - M);
        float L = pl[t] * e0 + pl[64 + t] * e1 + pl[128 + t] * e2 + pl[192 + t] * e3;
        float inv = 1.f / L;
        int qo = blockIdx.x * 64 + t;
#pragma unroll
        for (int d = 0; d < DH; d++) {
            float v = pac[t * 33 + d] * e0 + pac[(64 + t) * 33 + d] * e1 +
                      pac[(128 + t) * 33 + d] * e2 + pac[(192 + t) * 33 + d] * e3;
            g_ctx[(b * S + qo) * E + h * DH + d] = v * inv;
        }
    }
}

// ---------------- kernel 5: out_proj ----------------
__global__ void outproj_kernel(const float* __restrict__ ow, const float* __restrict__ ob) {
    extern __shared__ float sh[];
    float* cs = sh;
    float* ws = sh + 8320;
    const int t = threadIdx.x;
    const int chunk = blockIdx.x, stile = blockIdx.y, b = blockIdx.z;
    const int s0 = stile * 32;
    for (int p = 0; p < 8; p++) {
        int i4 = t + p * 256;
        int s = i4 >> 6, e4 = i4 & 63;
        *(float4*)&cs[s * 260 + 4 * e4] = *(const float4*)&g_ctx[(b * S + s0 + s) * E + 4 * e4];
    }
    for (int p = 0; p < 8; p++) {
        int i4 = t + p * 256;
        int o = i4 >> 6, k4 = i4 & 63;
        *(float4*)&ws[o * 268 + 4 * k4] = *(const float4*)&ow[(chunk * 32 + o) * 256 + 4 * k4];
    }
    __syncthreads();
    const int ol = t & 31, sb = (t >> 5) * 4;
    float acc[4] = {0.f, 0.f, 0.f, 0.f};
#pragma unroll 8
    for (int k4 = 0; k4 < 64; k4++) {
        float4 wv = *(float4*)&ws[ol * 268 + 4 * k4];
#pragma unroll
        for (int i = 0; i < 4; i++) {
            float4 av = *(float4*)&cs[(sb + i) * 260 + 4 * k4];
            acc[i] += wv.x * av.x + wv.y * av.y + wv.z * av.z + wv.w * av.w;
        }
    }
    const int og = chunk * 32 + ol;
    const float bb = ob[og];
#pragma unroll
    for (int i = 0; i < 4; i++)
        g_attn[(b * S + s0 + sb + i) * E + og] = acc[i] + bb;
}

// ---------------- kernel 6: fp16 2-term mma.sync point-MLP ----------------
// A buffers (hi only): 2 x [128 rows][72 fp16] stride 144B; h3 overlays them after stage2.
#define AB(i)   ((i) ? 18432 : 0)
#define MT_H3   0                     // overlay: 128*67*4 = 34304 <= 36864
#define MT_BI2  36864                 // 512
#define MT_BI3  37376                 // 256
#define MT_W4S  37632                 // 512
#define MT_PREF 38144                 // 1028
#define MT_CID  39172                 // 512
#define MT_SIZE 39936

__global__ __launch_bounds__(256)
void mlp_mma_kernel(const float* __restrict__ lo, const float* __restrict__ w4,
                    const float* __restrict__ b4, float* __restrict__ out) {
    extern __shared__ __align__(16) char smc[];
    float* h3f  = (float*)(smc + MT_H3);
    float* bi2s = (float*)(smc + MT_BI2);
    float* bi3s = (float*)(smc + MT_BI3);
    float* w4s  = (float*)(smc + MT_W4S);
    int*   pref = (int*)(smc + MT_PREF);
    int*   cid  = (int*)(smc + MT_CID);
    const unsigned smemB = (unsigned)__cvta_generic_to_shared(smc);

    const int t = threadIdx.x;
    const int w = t >> 5, lane = t & 31;
    const int b = blockIdx.y;
    const int n0 = blockIdx.x * 128;

    if (t < 128) { bi2s[t] = g_bi2[t]; w4s[t] = w4[t]; }
    if (t >= 128 && t < 192) bi3s[t - 128] = g_bi3[t - 128];
    if (t < 256) pref[t] = g_pref[t];
    __syncthreads();
    if (t < 128) {
        int i = n0 + t;
        int s = 0;
#pragma unroll
        for (int step = 128; step >= 1; step >>= 1)
            if (s + step <= 255 && pref[s + step] <= i) s += step;
        cid[t] = s;
    }
    __syncthreads();

    // gather mapping: row = t>>1 (0-127), kh = (t&1)*32
    const int grow = t >> 1, gkh = (t & 1) * 32;
    // ldmatrix lane addressing
    const int arow = (lane & 7) + ((lane >> 3) & 1) * 8;
    const int akb  = (lane >> 4) * 16;
    // stage1 warp tiling: 64 pts x 32 ch
    const int wm = w >> 2, wn = w & 3;

    float acc[4][4][4];
#pragma unroll
    for (int mt = 0; mt < 4; mt++)
#pragma unroll
        for (int nt = 0; nt < 4; nt++)
#pragma unroll
            for (int r = 0; r < 4; r++) acc[mt][nt][r] = 0.f;

    // ---- gather chunk 0 (hi only) ----
    {
        const float* src = lo + ((size_t)(b * NN + n0 + grow)) * LD + gkh;
        unsigned hb = smemB + AB(0) + grow * 144 + gkh * 2;
#pragma unroll
        for (int j = 0; j < 8; j++) {
            float4 v = *(const float4*)(src + 4 * j);
            sts64(hb + 8 * j, pack2h(v.x, v.y), pack2h(v.z, v.w));
        }
    }
    __syncthreads();

    // ---- stage 1: 6 chunks of K=64, 2-term (Ah*Wh + Ah*Wl) ----
    for (int c = 0; c < 6; c++) {
        // prefetch next chunk into registers (hidden under mma below)
        float4 nxt[8];
        if (c < 5) {
            const int nc = c + 1;
            const float* src = (nc < 2)
                ? (lo + ((size_t)(b * NN + n0 + grow)) * LD + nc * 64 + gkh)
                : (g_attn + ((size_t)(b * S + cid[grow])) * E + (nc - 2) * 64 + gkh);
#pragma unroll
            for (int j = 0; j < 8; j++) nxt[j] = *(const float4*)(src + 4 * j);
        }

        const unsigned ah = smemB + AB(c & 1);
#pragma unroll
        for (int ks = 0; ks < 4; ks++) {
            uint2 bh[4], bl[4];
#pragma unroll
            for (int nt = 0; nt < 4; nt++) {
                int idx = ((c * 4 + ks) * 16 + wn * 4 + nt) * 32 + lane;
                bh[nt] = __ldg(&g_w2fh[idx]);
                bl[nt] = __ldg(&g_w2fl[idx]);
            }
#pragma unroll
            for (int mt = 0; mt < 4; mt++) {
                unsigned base = (wm * 64 + mt * 16 + arow) * 144 + ks * 32 + akb;
                unsigned fah[4];
                ldmx4(fah, ah + base);
#pragma unroll
                for (int nt = 0; nt < 4; nt++) {
                    mma_f16(acc[mt][nt][0], acc[mt][nt][1], acc[mt][nt][2], acc[mt][nt][3],
                            fah, bh[nt].x, bh[nt].y);
                    mma_f16(acc[mt][nt][0], acc[mt][nt][1], acc[mt][nt][2], acc[mt][nt][3],
                            fah, bl[nt].x, bl[nt].y);
                }
            }
        }
        if (c < 5) {
            unsigned hb = smemB + AB((c + 1) & 1) + grow * 144 + gkh * 2;
#pragma unroll
            for (int j = 0; j < 8; j++)
                sts64(hb + 8 * j, pack2h(nxt[j].x, nxt[j].y), pack2h(nxt[j].z, nxt[j].w));
        }
        __syncthreads();
    }

    // ---- stage1 epilogue: bias+relu -> fp16 h2 into A buffers (ch0-63 buf0, ch64-127 buf1) ----
    {
        const int g = lane >> 2, tg = lane & 3;
#pragma unroll
        for (int mt = 0; mt < 4; mt++) {
#pragma unroll
            for (int nt = 0; nt < 4; nt++) {
                int col = wn * 32 + nt * 8 + 2 * tg;
                int bufi = col >> 6;
                unsigned off = (col & 63) * 2;
                float bia = bi2s[col], bib = bi2s[col + 1];
                int r0 = wm * 64 + mt * 16 + g;
                float v0 = fmaxf(acc[mt][nt][0] + bia, 0.f);
                float v1 = fmaxf(acc[mt][nt][1] + bib, 0.f);
                *(unsigned*)(smc + AB(bufi) + r0 * 144 + off) = pack2h(v0, v1);
                int r1 = r0 + 8;
                float v2 = fmaxf(acc[mt][nt][2] + bia, 0.f);
                float v3 = fmaxf(acc[mt][nt][3] + bib, 0.f);
                *(unsigned*)(smc + AB(bufi) + r1 * 144 + off) = pack2h(v2, v3);
            }
        }
    }
    __syncthreads();

    // ---- stage 2: K=128 (8 ksteps), warp tile 32 pts x 32 ch, 2-term ----
    const int wm2 = w >> 1, wn2 = w & 1;
    float ac2[2][4][4];
#pragma unroll
    for (int mt = 0; mt < 2; mt++)
#pragma unroll
        for (int nt = 0; nt < 4; nt++)
#pragma unroll
            for (int r = 0; r < 4; r++) ac2[mt][nt][r] = 0.f;

#pragma unroll
    for (int ks = 0; ks < 8; ks++) {
        const unsigned ah = smemB + AB(ks >> 2);
        const int ki = ks & 3;
        uint2 bh[4], bl[4];
#pragma unroll
        for (int nt = 0; nt < 4; nt++) {
            int idx = (ks * 8 + wn2 * 4 + nt) * 32 + lane;
            bh[nt] = __ldg(&g_w3fh[idx]);
            bl[nt] = __ldg(&g_w3fl[idx]);
        }
#pragma unroll
        for (int mt = 0; mt < 2; mt++) {
            unsigned base = (wm2 * 32 + mt * 16 + arow) * 144 + ki * 32 + akb;
            unsigned fah[4];
            ldmx4(fah, ah + base);
#pragma unroll
            for (int nt = 0; nt < 4; nt++) {
                mma_f16(ac2[mt][nt][0], ac2[mt][nt][1], ac2[mt][nt][2], ac2[mt][nt][3],
                        fah, bh[nt].x, bh[nt].y);
                mma_f16(ac2[mt][nt][0], ac2[mt][nt][1], ac2[mt][nt][2], ac2[mt][nt][3],
                        fah, bl[nt].x, bl[nt].y);
            }
        }
    }
    __syncthreads();   // all stage2 reads of A buffers done before h3 overlay

    // ---- stage2 epilogue: h3 fp32 overlay ----
    {
        const int g = lane >> 2, tg = lane & 3;
#pragma unroll
        for (int mt = 0; mt < 2; mt++) {
#pragma unroll
            for (int nt = 0; nt < 4; nt++) {
                int col = wn2 * 32 + nt * 8 + 2 * tg;
                float bia = bi3s[col], bib = bi3s[col + 1];
                int r0 = wm2 * 32 + mt * 16 + g;
                h3f[r0 * 67 + col]     = fmaxf(ac2[mt][nt][0] + bia, 0.f);
                h3f[r0 * 67 + col + 1] = fmaxf(ac2[mt][nt][1] + bib, 0.f);
                int r1 = r0 + 8;
                h3f[r1 * 67 + col]     = fmaxf(ac2[mt][nt][2] + bia, 0.f);
                h3f[r1 * 67 + col + 1] = fmaxf(ac2[mt][nt][3] + bib, 0.f);
            }
        }
    }
    __syncthreads();

    // ---- conv4 + transposed write ----
    if (t < 128) {
        const int p = t;
        float a0 = b4[0], a1 = b4[1];
#pragma unroll
        for (int k = 0; k < 64; k++) {
            float v = h3f[p * 67 + k];
            a0 += v * w4s[k];
            a1 += v * w4s[64 + k];
        }
        out[(size_t)(b * NC + 0) * NN + n0 + p] = a0;
        out[(size_t)(b * NC + 1) * NN + n0 + p] = a1;
    }
}

// ---------------- launch ----------------
extern "C" void kernel_launch(void* const* d_in, const int* in_sizes, int n_in,
                              void* d_out, int out_size) {
    const float* gl   = (const float*)d_in[0];
    const float* lo   = (const float*)d_in[1];
    const float* cent = (const float*)d_in[2];
    const int*   npc  = (const int*)  d_in[3];
    const float* fc1w = (const float*)d_in[4];
    const float* fc1b = (const float*)d_in[5];
    const float* fc2w = (const float*)d_in[6];
    const float* fc2b = (const float*)d_in[7];
    const float* inw  = (const float*)d_in[8];
    const float* inb  = (const float*)d_in[9];
    const float* ow   = (const float*)d_in[10];
    const float* ob   = (const float*)d_in[11];
    const float* w2   = (const float*)d_in[12];
    const float* cb2  = (const float*)d_in[13];
    const float* gm2  = (const float*)d_in[14];
    const float* bt2  = (const float*)d_in[15];
    const float* mu2  = (const float*)d_in[16];
    const float* va2  = (const float*)d_in[17];
    const float* w3   = (const float*)d_in[18];
    const float* cb3  = (const float*)d_in[19];
    const float* gm3  = (const float*)d_in[20];
    const float* bt3  = (const float*)d_in[21];
    const float* mu3  = (const float*)d_in[22];
    const float* va3  = (const float*)d_in[23];
    const float* w4   = (const float*)d_in[24];
    const float* b4   = (const float*)d_in[25];
    float* out = (float*)d_out;

    const int xqkv_smem = (8320 + 17152) * 4;
    const int attn_smem = (8192 * 2 + 256 * 2 + 8448) * 4;
    const int outp_smem = (8320 + 8576) * 4;

    cudaFuncSetAttribute(xqkv_kernel,    cudaFuncAttributeMaxDynamicSharedMemorySize, xqkv_smem);
    cudaFuncSetAttribute(attn_kernel,    cudaFuncAttributeMaxDynamicSharedMemorySize, attn_smem);
    cudaFuncSetAttribute(outproj_kernel, cudaFuncAttributeMaxDynamicSharedMemorySize, outp_smem);
    cudaFuncSetAttribute(mlp_mma_kernel, cudaFuncAttributeMaxDynamicSharedMemorySize, MT_SIZE);

    prep_kernel<<<1, 256>>>(npc);
    wfrag2_kernel<<<48, 256>>>(w2, cb2, gm2, bt2, mu2, va2);
    wfrag3_kernel<<<8, 256>>>(w3, cb3, gm3, bt3, mu3, va3);
    xk_kernel<<<dim3(8, B), 256>>>(gl, cent, fc1w, fc1b, fc2w, fc2b);
    xqkv_kernel<<<dim3(12, 8, B), 256, xqkv_smem>>>(inw, inb);
    attn_kernel<<<dim3(4, H, B), 256, attn_smem>>>();
    outproj_kernel<<<dim3(8, 8, B), 256, outp_smem>>>(ow, ob);
    mlp_mma_kernel<<<dim3(NN / 128, B), 256, MT_SIZE>>>(lo, w4, b4, out);
}

// round 10
// speedup vs baseline: 8.3626x; 1.6267x over previous
#include <cuda_runtime.h>
#include <cuda_fp16.h>
#include <math.h>

#define B 4
#define S 256
#define E 256
#define H 8
#define DH 32
#define LD 128
#define NN 65536
#define NC 2
#define EPS 1e-5f

// ---------------- scratch ----------------
__device__ __align__(16) float g_q[B*H*S*DH];
__device__ __align__(16) float g_k[B*H*S*DH];
__device__ __align__(16) float g_v[B*H*S*DH];
__device__ __align__(16) float g_ctx[B*S*E];
__device__ __align__(16) float g_attn[B*S*E];
__device__ __align__(16) float g_x[B*S*E];
__device__ __align__(16) float g_gpb[B*S*128];   // attn_out @ W2_global + bi2 (per cluster)
__device__ int g_pref[S + 1];
// W2 local-half folded+split fp16, fragment-major: [chunk2][kstep4][ntile16][lane32] uint2
__device__ __align__(16) uint2 g_w2fh[2*4*16*32];
__device__ __align__(16) uint2 g_w2fl[2*4*16*32];
// W3 folded+split fp16, fragment-major: [kstep8][ntile8][lane32]
__device__ __align__(16) uint2 g_w3fh[8*8*32];
__device__ __align__(16) uint2 g_w3fl[8*8*32];
__device__ float g_bi3[64];

// ---------------- helpers ----------------
__device__ __forceinline__ unsigned pack2h(float a0, float a1) {
    __half2 h = __floats2half2_rn(a0, a1);
    return *reinterpret_cast<unsigned*>(&h);
}
__device__ __forceinline__ unsigned pack_split2h(float a0, float a1, unsigned &lo2) {
    __half h0 = __float2half_rn(a0), h1 = __float2half_rn(a1);
    __half l0 = __float2half_rn(a0 - __half2float(h0));
    __half l1 = __float2half_rn(a1 - __half2float(h1));
    lo2 = ((unsigned)__half_as_ushort(l1) << 16) | (unsigned)__half_as_ushort(l0);
    return ((unsigned)__half_as_ushort(h1) << 16) | (unsigned)__half_as_ushort(h0);
}
__device__ __forceinline__ void sts64(unsigned a, unsigned x, unsigned y) {
    asm volatile("st.shared.v2.b32 [%0],{%1,%2};" :: "r"(a), "r"(x), "r"(y) : "memory");
}
__device__ __forceinline__ void ldmx4(unsigned* r, unsigned addr) {
    asm volatile("ldmatrix.sync.aligned.m8n8.x4.shared.b16 {%0,%1,%2,%3},[%4];"
                 : "=r"(r[0]), "=r"(r[1]), "=r"(r[2]), "=r"(r[3]) : "r"(addr));
}
__device__ __forceinline__ void mma_f16(float &d0, float &d1, float &d2, float &d3,
                                        const unsigned* a, unsigned b0, unsigned b1) {
    asm volatile("mma.sync.aligned.m16n8k16.row.col.f32.f16.f16.f32 "
                 "{%0,%1,%2,%3},{%4,%5,%6,%7},{%8,%9},{%0,%1,%2,%3};"
                 : "+f"(d0), "+f"(d1), "+f"(d2), "+f"(d3)
                 : "r"(a[0]), "r"(a[1]), "r"(a[2]), "r"(a[3]), "r"(b0), "r"(b1));
}

// ---------------- kernel 1: prefix sums ----------------
__global__ void prep_kernel(const int* __restrict__ npc) {
    __shared__ int vals[S];
    int t = threadIdx.x;
    vals[t] = npc[t];
    __syncthreads();
    if (t == 0) {
        int a = 0;
        for (int s = 0; s < S; s++) { g_pref[s] = a; a += vals[s]; }
        g_pref[S] = a;
    }
}

// ---------------- kernel 1b: W2 local half -> folded/split fp16 fragment-major ----------------
__global__ void wfrag2_kernel(const float* __restrict__ w2,
                              const float* __restrict__ gm2, const float* __restrict__ va2) {
    int id = blockIdx.x * 256 + threadIdx.x;
    if (id >= 2*4*16*32) return;
    int lane = id & 31;
    int nt = (id >> 5) & 15;
    int ks = (id >> 9) & 3;
    int ch = id >> 11;                 // chunk 0-1 (K cols 0-127 of w2)
    int n = nt * 8 + (lane >> 2);
    int k0 = ch * 64 + ks * 16 + 2 * (lane & 3);
    float s = gm2[n] * rsqrtf(va2[n] + EPS);
    float v0 = w2[n * 384 + k0] * s,     v1 = w2[n * 384 + k0 + 1] * s;
    float v2 = w2[n * 384 + k0 + 8] * s, v3 = w2[n * 384 + k0 + 9] * s;
    unsigned l0, l1;
    unsigned h0 = pack_split2h(v0, v1, l0);
    unsigned h1 = pack_split2h(v2, v3, l1);
    g_w2fh[id] = make_uint2(h0, h1);
    g_w2fl[id] = make_uint2(l0, l1);
}

// ---------------- kernel 1c: W3 -> folded/split fp16 fragment-major ----------------
__global__ void wfrag3_kernel(const float* __restrict__ w3, const float* __restrict__ cb3,
                              const float* __restrict__ gm3, const float* __restrict__ bt3,
                              const float* __restrict__ mu3, const float* __restrict__ va3) {
    int id = blockIdx.x * 256 + threadIdx.x;
    if (id >= 8*8*32) return;
    int lane = id & 31;
    int nt = (id >> 5) & 7;
    int ks = id >> 8;
    int n = nt * 8 + (lane >> 2);
    int k0 = ks * 16 + 2 * (lane & 3);
    float s = gm3[n] * rsqrtf(va3[n] + EPS);
    if (ks == 0 && (lane & 3) == 0)
        g_bi3[n] = (cb3[n] - mu3[n]) * s + bt3[n];
    float v0 = w3[n * 128 + k0] * s,     v1 = w3[n * 128 + k0 + 1] * s;
    float v2 = w3[n * 128 + k0 + 8] * s, v3 = w3[n * 128 + k0 + 9] * s;
    unsigned l0, l1;
    unsigned h0 = pack_split2h(v0, v1, l0);
    unsigned h1 = pack_split2h(v2, v3, l1);
    g_w3fh[id] = make_uint2(h0, h1);
    g_w3fl[id] = make_uint2(l0, l1);
}

// ---------------- kernel 2: x = gl^T + pos(centroids), grid (S,B) x 256 ----------------
__global__ void xk_kernel(const float* __restrict__ gl, const float* __restrict__ cent,
                          const float* __restrict__ fc1w, const float* __restrict__ fc1b,
                          const float* __restrict__ fc2w, const float* __restrict__ fc2b) {
    const int s = blockIdx.x, b = blockIdx.y, e = threadIdx.x;
    const float c0 = cent[(b * S + s) * 2 + 0];
    const float c1 = cent[(b * S + s) * 2 + 1];
    float pos = fc2b[e];
#pragma unroll
    for (int j = 0; j < 16; j++) {
        float hh = fc1b[j] + c0 * fc1w[2 * j] + c1 * fc1w[2 * j + 1];
        hh = (hh >= 0.f) ? hh : 0.01f * hh;
        pos += hh * fc2w[e * 16 + j];
    }
    g_x[(b * S + s) * E + e] = gl[(s * B + b) * E + e] + pos;
}

// ---------------- kernel 3: qkv ----------------
__global__ void xqkv_kernel(const float* __restrict__ inw, const float* __restrict__ inb) {
    extern __shared__ float sh[];
    float* xs = sh;
    float* ws = sh + 8320;
    const int t = threadIdx.x;
    const int chunk = blockIdx.x, stile = blockIdx.y, b = blockIdx.z;
    const int s0 = stile * 32;
    for (int p = 0; p < 8; p++) {
        int i4 = t + p * 256;
        int s = i4 >> 6, e4 = i4 & 63;
        *(float4*)&xs[s * 260 + 4 * e4] = *(const float4*)&g_x[(b * S + s0 + s) * E + 4 * e4];
    }
    for (int p = 0; p < 16; p++) {
        int i4 = t + p * 256;
        int o = i4 >> 6, k4 = i4 & 63;
        *(float4*)&ws[o * 268 + 4 * k4] = *(const float4*)&inw[(chunk * 64 + o) * 256 + 4 * k4];
    }
    __syncthreads();
    const int ol = t & 63, sb = (t >> 6) * 8;
    float acc[8];
#pragma unroll
    for (int i = 0; i < 8; i++) acc[i] = 0.f;
#pragma unroll 8
    for (int k4 = 0; k4 < 64; k4++) {
        float4 wv = *(float4*)&ws[ol * 268 + 4 * k4];
#pragma unroll
        for (int i = 0; i < 8; i++) {
            float4 av = *(float4*)&xs[(sb + i) * 260 + 4 * k4];
            acc[i] += wv.x * av.x + wv.y * av.y + wv.z * av.z + wv.w * av.w;
        }
    }
    const int og = chunk * 64 + ol;
    const float bb = inb[og];
    const int part = og >> 8, e = og & 255, hh = e >> 5, d = e & 31;
    float* dst = (part == 0) ? g_q : ((part == 1) ? g_k : g_v);
#pragma unroll
    for (int i = 0; i < 8; i++) {
        int s = s0 + sb + i;
        dst[((b * H + hh) * S + s) * DH + d] = acc[i] + bb;
    }
}

// ---------------- kernel 4: attention ----------------
__global__ void attn_kernel() {
    extern __shared__ float sh[];
    float* ks  = sh;
    float* vs  = sh + 8192;
    float* pm  = vs + 8192;
    float* pl  = pm + 256;
    float* pac = pl + 256;
    const int t = threadIdx.x;
    const int b = blockIdx.z, h = blockIdx.y;
    const int base = ((b * H + h) * S) * DH;
    for (int i = t; i < 2048; i += 256) {
        ((float4*)ks)[i] = ((const float4*)(g_k + base))[i];
        ((float4*)vs)[i] = ((const float4*)(g_v + base))[i];
    }
    __syncthreads();
    const int q = t & 63, jh = t >> 6;
    const int qg = blockIdx.x * 64 + q;
    float qr[DH];
#pragma unroll
    for (int i = 0; i < 8; i++) ((float4*)qr)[i] = ((const float4*)(g_q + base + qg * DH))[i];
    const float scale = 0.17677669529663687f;
    float m = -1e30f, l = 0.f, acc[DH];
#pragma unroll
    for (int d = 0; d < DH; d++) acc[d] = 0.f;
    for (int j = jh * 64; j < jh * 64 + 64; j++) {
        float sc = 0.f;
#pragma unroll
        for (int d = 0; d < DH; d++) sc += qr[d] * ks[j * DH + d];
        sc *= scale;
        float mn = fmaxf(m, sc);
        float corr = __expf(m - mn);
        float p = __expf(sc - mn);
        m = mn;
        l = l * corr + p;
#pragma unroll
        for (int d = 0; d < DH; d++) acc[d] = acc[d] * corr + p * vs[j * DH + d];
    }
    pm[jh * 64 + q] = m;
    pl[jh * 64 + q] = l;
#pragma unroll
    for (int d = 0; d < DH; d++) pac[(jh * 64 + q) * 33 + d] = acc[d];
    __syncthreads();
    if (t < 64) {
        float M = pm[t];
#pragma unroll
        for (int i = 1; i < 4; i++) M = fmaxf(M, pm[i * 64 + t]);
        float e0 = __expf(pm[t] - M), e1 = __expf(pm[64 + t] - M),
              e2 = __expf(pm[128 + t] - M), e3 = __expf(pm[192 + t] - M);
        float L = pl[t] * e0 + pl[64 + t] * e1 + pl[128 + t] * e2 + pl[192 + t] * e3;
        float inv = 1.f / L;
        int qo = blockIdx.x * 64 + t;
#pragma unroll
        for (int d = 0; d < DH; d++) {
            float v = pac[t * 33 + d] * e0 + pac[(64 + t) * 33 + d] * e1 +
                      pac[(128 + t) * 33 + d] * e2 + pac[(192 + t) * 33 + d] * e3;
            g_ctx[(b * S + qo) * E + h * DH + d] = v * inv;
        }
    }
}

// ---------------- kernel 5: out_proj ----------------
__global__ void outproj_kernel(const float* __restrict__ ow, const float* __restrict__ ob) {
    extern __shared__ float sh[];
    float* cs = sh;
    float* ws = sh + 8320;
    const int t = threadIdx.x;
    const int chunk = blockIdx.x, stile = blockIdx.y, b = blockIdx.z;
    const int s0 = stile * 32;
    for (int p = 0; p < 8; p++) {
        int i4 = t + p * 256;
        int s = i4 >> 6, e4 = i4 & 63;
        *(float4*)&cs[s * 260 + 4 * e4] = *(const float4*)&g_ctx[(b * S + s0 + s) * E + 4 * e4];
    }
    for (int p = 0; p < 8; p++) {
        int i4 = t + p * 256;
        int o = i4 >> 6, k4 = i4 & 63;
        *(float4*)&ws[o * 268 + 4 * k4] = *(const float4*)&ow[(chunk * 32 + o) * 256 + 4 * k4];
    }
    __syncthreads();
    const int ol = t & 31, sb = (t >> 5) * 4;
    float acc[4] = {0.f, 0.f, 0.f, 0.f};
#pragma unroll 8
    for (int k4 = 0; k4 < 64; k4++) {
        float4 wv = *(float4*)&ws[ol * 268 + 4 * k4];
#pragma unroll
        for (int i = 0; i < 4; i++) {
            float4 av = *(float4*)&cs[(sb + i) * 260 + 4 * k4];
            acc[i] += wv.x * av.x + wv.y * av.y + wv.z * av.z + wv.w * av.w;
        }
    }
    const int og = chunk * 32 + ol;
    const float bb = ob[og];
#pragma unroll
    for (int i = 0; i < 4; i++)
        g_attn[(b * S + s0 + sb + i) * E + og] = acc[i] + bb;
}

// ---------------- kernel 5b: gpb = attn_out @ W2_global^T (folded) + bi2, per cluster ----------------
// grid (4 chunks of 32 cols, 8 stiles, B) x 256
__global__ void gproj_kernel(const float* __restrict__ w2, const float* __restrict__ cb2,
                             const float* __restrict__ gm2, const float* __restrict__ bt2,
                             const float* __restrict__ mu2, const float* __restrict__ va2) {
    extern __shared__ float sh[];
    float* cs = sh;          // 32*260
    float* ws = sh + 8320;   // 32*268
    const int t = threadIdx.x;
    const int chunk = blockIdx.x, stile = blockIdx.y, b = blockIdx.z;
    const int s0 = stile * 32;
    for (int p = 0; p < 8; p++) {
        int i4 = t + p * 256;
        int s = i4 >> 6, e4 = i4 & 63;
        *(float4*)&cs[s * 260 + 4 * e4] = *(const float4*)&g_attn[(b * S + s0 + s) * E + 4 * e4];
    }
    for (int p = 0; p < 8; p++) {
        int i4 = t + p * 256;
        int o = i4 >> 6, k4 = i4 & 63;
        int oc = chunk * 32 + o;
        float s = gm2[oc] * rsqrtf(va2[oc] + EPS);
        float4 v = *(const float4*)&w2[oc * 384 + 128 + 4 * k4];
        v.x *= s; v.y *= s; v.z *= s; v.w *= s;
        *(float4*)&ws[o * 268 + 4 * k4] = v;
    }
    __syncthreads();
    const int ol = t & 31, sb = (t >> 5) * 4;
    float acc[4] = {0.f, 0.f, 0.f, 0.f};
#pragma unroll 8
    for (int k4 = 0; k4 < 64; k4++) {
        float4 wv = *(float4*)&ws[ol * 268 + 4 * k4];
#pragma unroll
        for (int i = 0; i < 4; i++) {
            float4 av = *(float4*)&cs[(sb + i) * 260 + 4 * k4];
            acc[i] += wv.x * av.x + wv.y * av.y + wv.z * av.z + wv.w * av.w;
        }
    }
    const int og = chunk * 32 + ol;
    float s = gm2[og] * rsqrtf(va2[og] + EPS);
    const float bb = (cb2[og] - mu2[og]) * s + bt2[og];
#pragma unroll
    for (int i = 0; i < 4; i++)
        g_gpb[(b * S + s0 + sb + i) * 128 + og] = acc[i] + bb;
}

// ---------------- kernel 6: fp16 2-term mma.sync point-MLP (K=128 local + gpb init) ----------------
#define AB(i)   ((i) ? 18432 : 0)
#define MT_H3   0                     // overlay: 128*67*4 = 34304 <= 36864
#define MT_BI3  36864                 // 256
#define MT_W4S  37120                 // 512
#define MT_PREF 37632                 // 1028
#define MT_CID  38660                 // 512
#define MT_SIZE 39424

__global__ __launch_bounds__(256)
void mlp_mma_kernel(const float* __restrict__ lo, const float* __restrict__ w4,
                    const float* __restrict__ b4, float* __restrict__ out) {
    extern __shared__ __align__(16) char smc[];
    float* h3f  = (float*)(smc + MT_H3);
    float* bi3s = (float*)(smc + MT_BI3);
    float* w4s  = (float*)(smc + MT_W4S);
    int*   pref = (int*)(smc + MT_PREF);
    int*   cid  = (int*)(smc + MT_CID);
    const unsigned smemB = (unsigned)__cvta_generic_to_shared(smc);

    const int t = threadIdx.x;
    const int w = t >> 5, lane = t & 31;
    const int b = blockIdx.y;
    const int n0 = blockIdx.x * 128;

    if (t < 128) w4s[t] = w4[t];
    if (t >= 128 && t < 192) bi3s[t - 128] = g_bi3[t - 128];
    if (t < 256) pref[t] = g_pref[t];
    __syncthreads();
    if (t < 128) {
        int i = n0 + t;
        int s = 0;
#pragma unroll
        for (int step = 128; step >= 1; step >>= 1)
            if (s + step <= 255 && pref[s + step] <= i) s += step;
        cid[t] = s;
    }
    __syncthreads();

    // gather mapping: row = t>>1 (0-127), kh = (t&1)*32
    const int grow = t >> 1, gkh = (t & 1) * 32;
    // ldmatrix lane addressing
    const int arow = (lane & 7) + ((lane >> 3) & 1) * 8;
    const int akb  = (lane >> 4) * 16;
    // stage1 warp tiling: 64 pts x 32 ch
    const int wm = w >> 2, wn = w & 3;
    const int g = lane >> 2, tg = lane & 3;

    // ---- gather chunk 0 (lo k 0-63) ----
    {
        const float* src = lo + ((size_t)(b * NN + n0 + grow)) * LD + gkh;
        unsigned hb = smemB + AB(0) + grow * 144 + gkh * 2;
#pragma unroll
        for (int j = 0; j < 8; j++) {
            float4 v = *(const float4*)(src + 4 * j);
            sts64(hb + 8 * j, pack2h(v.x, v.y), pack2h(v.z, v.w));
        }
    }

    // ---- init accumulators from gpb[cid] (the precomputed global-half, fp32-exact) ----
    float acc[4][4][4];
#pragma unroll
    for (int mt = 0; mt < 4; mt++) {
        int r0 = wm * 64 + mt * 16 + g;
        const float* g0 = g_gpb + ((size_t)(b * S + cid[r0])) * 128;
        const float* g1 = g_gpb + ((size_t)(b * S + cid[r0 + 8])) * 128;
#pragma unroll
        for (int nt = 0; nt < 4; nt++) {
            int col = wn * 32 + nt * 8 + 2 * tg;
            float2 v0 = *(const float2*)(g0 + col);
            float2 v1 = *(const float2*)(g1 + col);
            acc[mt][nt][0] = v0.x; acc[mt][nt][1] = v0.y;
            acc[mt][nt][2] = v1.x; acc[mt][nt][3] = v1.y;
        }
    }
    __syncthreads();

    // ---- stage 1: 2 chunks of K=64 (lo only), 2-term (Ah*Wh + Ah*Wl) ----
    for (int c = 0; c < 2; c++) {
        float4 nxt[8];
        if (c == 0) {
            const float* src = lo + ((size_t)(b * NN + n0 + grow)) * LD + 64 + gkh;
#pragma unroll
            for (int j = 0; j < 8; j++) nxt[j] = *(const float4*)(src + 4 * j);
        }
        const unsigned ah = smemB + AB(c);
#pragma unroll
        for (int ks = 0; ks < 4; ks++) {
            uint2 bh[4], bl[4];
#pragma unroll
            for (int nt = 0; nt < 4; nt++) {
                int idx = ((c * 4 + ks) * 16 + wn * 4 + nt) * 32 + lane;
                bh[nt] = __ldg(&g_w2fh[idx]);
                bl[nt] = __ldg(&g_w2fl[idx]);
            }
#pragma unroll
            for (int mt = 0; mt < 4; mt++) {
                unsigned base = (wm * 64 + mt * 16 + arow) * 144 + ks * 32 + akb;
                unsigned fah[4];
                ldmx4(fah, ah + base);
#pragma unroll
                for (int nt = 0; nt < 4; nt++) {
                    mma_f16(acc[mt][nt][0], acc[mt][nt][1], acc[mt][nt][2], acc[mt][nt][3],
                            fah, bh[nt].x, bh[nt].y);
                    mma_f16(acc[mt][nt][0], acc[mt][nt][1], acc[mt][nt][2], acc[mt][nt][3],
                            fah, bl[nt].x, bl[nt].y);
                }
            }
        }
        if (c == 0) {
            unsigned hb = smemB + AB(1) + grow * 144 + gkh * 2;
#pragma unroll
            for (int j = 0; j < 8; j++)
                sts64(hb + 8 * j, pack2h(nxt[j].x, nxt[j].y), pack2h(nxt[j].z, nxt[j].w));
        }
        __syncthreads();
    }

    // ---- stage1 epilogue: relu -> fp16 h2 into A buffers (ch0-63 buf0, ch64-127 buf1) ----
    {
#pragma unroll
        for (int mt = 0; mt < 4; mt++) {
#pragma unroll
            for (int nt = 0; nt < 4; nt++) {
                int col = wn * 32 + nt * 8 + 2 * tg;
                int bufi = col >> 6;
                unsigned off = (col & 63) * 2;
                int r0 = wm * 64 + mt * 16 + g;
                float v0 = fmaxf(acc[mt][nt][0], 0.f);
                float v1 = fmaxf(acc[mt][nt][1], 0.f);
                *(unsigned*)(smc + AB(bufi) + r0 * 144 + off) = pack2h(v0, v1);
                int r1 = r0 + 8;
                float v2 = fmaxf(acc[mt][nt][2], 0.f);
                float v3 = fmaxf(acc[mt][nt][3], 0.f);
                *(unsigned*)(smc + AB(bufi) + r1 * 144 + off) = pack2h(v2, v3);
            }
        }
    }
    __syncthreads();

    // ---- stage 2: K=128 (8 ksteps), warp tile 32 pts x 32 ch, 2-term ----
    const int wm2 = w >> 1, wn2 = w & 1;
    float ac2[2][4][4];
#pragma unroll
    for (int mt = 0; mt < 2; mt++)
#pragma unroll
        for (int nt = 0; nt < 4; nt++)
#pragma unroll
            for (int r = 0; r < 4; r++) ac2[mt][nt][r] = 0.f;

#pragma unroll
    for (int ks = 0; ks < 8; ks++) {
        const unsigned ah = smemB + AB(ks >> 2);
        const int ki = ks & 3;
        uint2 bh[4], bl[4];
#pragma unroll
        for (int nt = 0; nt < 4; nt++) {
            int idx = (ks * 8 + wn2 * 4 + nt) * 32 + lane;
            bh[nt] = __ldg(&g_w3fh[idx]);
            bl[nt] = __ldg(&g_w3fl[idx]);
        }
#pragma unroll
        for (int mt = 0; mt < 2; mt++) {
            unsigned base = (wm2 * 32 + mt * 16 + arow) * 144 + ki * 32 + akb;
            unsigned fah[4];
            ldmx4(fah, ah + base);
#pragma unroll
            for (int nt = 0; nt < 4; nt++) {
                mma_f16(ac2[mt][nt][0], ac2[mt][nt][1], ac2[mt][nt][2], ac2[mt][nt][3],
                        fah, bh[nt].x, bh[nt].y);
                mma_f16(ac2[mt][nt][0], ac2[mt][nt][1], ac2[mt][nt][2], ac2[mt][nt][3],
                        fah, bl[nt].x, bl[nt].y);
            }
        }
    }
    __syncthreads();   // all stage2 reads of A buffers done before h3 overlay

    // ---- stage2 epilogue: h3 fp32 overlay ----
    {
#pragma unroll
        for (int mt = 0; mt < 2; mt++) {
#pragma unroll
            for (int nt = 0; nt < 4; nt++) {
                int col = wn2 * 32 + nt * 8 + 2 * tg;
                float bia = bi3s[col], bib = bi3s[col + 1];
                int r0 = wm2 * 32 + mt * 16 + g;
                h3f[r0 * 67 + col]     = fmaxf(ac2[mt][nt][0] + bia, 0.f);
                h3f[r0 * 67 + col + 1] = fmaxf(ac2[mt][nt][1] + bib, 0.f);
                int r1 = r0 + 8;
                h3f[r1 * 67 + col]     = fmaxf(ac2[mt][nt][2] + bia, 0.f);
                h3f[r1 * 67 + col + 1] = fmaxf(ac2[mt][nt][3] + bib, 0.f);
            }
        }
    }
    __syncthreads();

    // ---- conv4 + transposed write ----
    if (t < 128) {
        const int p = t;
        float a0 = b4[0], a1 = b4[1];
#pragma unroll
        for (int k = 0; k < 64; k++) {
            float v = h3f[p * 67 + k];
            a0 += v * w4s[k];
            a1 += v * w4s[64 + k];
        }
        out[(size_t)(b * NC + 0) * NN + n0 + p] = a0;
        out[(size_t)(b * NC + 1) * NN + n0 + p] = a1;
    }
}

// ---------------- launch ----------------
extern "C" void kernel_launch(void* const* d_in, const int* in_sizes, int n_in,
                              void* d_out, int out_size) {
    const float* gl   = (const float*)d_in[0];
    const float* lo   = (const float*)d_in[1];
    const float* cent = (const float*)d_in[2];
    const int*   npc  = (const int*)  d_in[3];
    const float* fc1w = (const float*)d_in[4];
    const float* fc1b = (const float*)d_in[5];
    const float* fc2w = (const float*)d_in[6];
    const float* fc2b = (const float*)d_in[7];
    const float* inw  = (const float*)d_in[8];
    const float* inb  = (const float*)d_in[9];
    const float* ow   = (const float*)d_in[10];
    const float* ob   = (const float*)d_in[11];
    const float* w2   = (const float*)d_in[12];
    const float* cb2  = (const float*)d_in[13];
    const float* gm2  = (const float*)d_in[14];
    const float* bt2  = (const float*)d_in[15];
    const float* mu2  = (const float*)d_in[16];
    const float* va2  = (const float*)d_in[17];
    const float* w3   = (const float*)d_in[18];
    const float* cb3  = (const float*)d_in[19];
    const float* gm3  = (const float*)d_in[20];
    const float* bt3  = (const float*)d_in[21];
    const float* mu3  = (const float*)d_in[22];
    const float* va3  = (const float*)d_in[23];
    const float* w4   = (const float*)d_in[24];
    const float* b4   = (const float*)d_in[25];
    float* out = (float*)d_out;

    const int xqkv_smem = (8320 + 17152) * 4;
    const int attn_smem = (8192 * 2 + 256 * 2 + 8448) * 4;
    const int outp_smem = (8320 + 8576) * 4;

    cudaFuncSetAttribute(xqkv_kernel,    cudaFuncAttributeMaxDynamicSharedMemorySize, xqkv_smem);
    cudaFuncSetAttribute(attn_kernel,    cudaFuncAttributeMaxDynamicSharedMemorySize, attn_smem);
    cudaFuncSetAttribute(outproj_kernel, cudaFuncAttributeMaxDynamicSharedMemorySize, outp_smem);
    cudaFuncSetAttribute(gproj_kernel,   cudaFuncAttributeMaxDynamicSharedMemorySize, outp_smem);
    cudaFuncSetAttribute(mlp_mma_kernel, cudaFuncAttributeMaxDynamicSharedMemorySize, MT_SIZE);

    prep_kernel<<<1, 256>>>(npc);
    wfrag2_kernel<<<16, 256>>>(w2, gm2, va2);
    wfrag3_kernel<<<8, 256>>>(w3, cb3, gm3, bt3, mu3, va3);
    xk_kernel<<<dim3(S, B), 256>>>(gl, cent, fc1w, fc1b, fc2w, fc2b);
    xqkv_kernel<<<dim3(12, 8, B), 256, xqkv_smem>>>(inw, inb);
    attn_kernel<<<dim3(4, H, B), 256, attn_smem>>>();
    outproj_kernel<<<dim3(8, 8, B), 256, outp_smem>>>(ow, ob);
    gproj_kernel<<<dim3(4, 8, B), 256, outp_smem>>>(w2, cb2, gm2, bt2, mu2, va2);
    mlp_mma_kernel<<<dim3(NN / 128, B), 256, MT_SIZE>>>(lo, w4, b4, out);
}

// round 11
// speedup vs baseline: 8.7901x; 1.0511x over previous
#include <cuda_runtime.h>
#include <cuda_fp16.h>
#include <math.h>

#define B 4
#define S 256
#define E 256
#define H 8
#define DH 32
#define LD 128
#define NN 65536
#define NC 2
#define EPS 1e-5f

// ---------------- scratch ----------------
__device__ __align__(16) float g_q[B*H*S*DH];
__device__ __align__(16) float g_k[B*H*S*DH];
__device__ __align__(16) float g_v[B*H*S*DH];
__device__ __align__(16) float g_ctx[B*S*E];
__device__ __align__(16) float g_x[B*S*E];
__device__ __align__(16) float g_gpb[B*S*128];     // per-cluster global-half of h2 pre-activation
__device__ __align__(16) float g_wcomb[128*256];   // W2g_fold @ ow
__device__ float g_bcomb[128];
__device__ int g_pref[S + 1];
// W2 local half folded fp16 (hi only), fragment-major: [chunk2][kstep4][ntile16][lane32] uint2
__device__ __align__(16) uint2 g_w2fh[2*4*16*32];
// W3 folded fp16 (hi only), fragment-major: [kstep8][ntile8][lane32]
__device__ __align__(16) uint2 g_w3fh[8*8*32];
__device__ float g_bi3[64];

// ---------------- helpers ----------------
__device__ __forceinline__ unsigned pack2h(float a0, float a1) {
    __half2 h = __floats2half2_rn(a0, a1);
    return *reinterpret_cast<unsigned*>(&h);
}
__device__ __forceinline__ void sts64(unsigned a, unsigned x, unsigned y) {
    asm volatile("st.shared.v2.b32 [%0],{%1,%2};" :: "r"(a), "r"(x), "r"(y) : "memory");
}
__device__ __forceinline__ void ldmx4(unsigned* r, unsigned addr) {
    asm volatile("ldmatrix.sync.aligned.m8n8.x4.shared.b16 {%0,%1,%2,%3},[%4];"
                 : "=r"(r[0]), "=r"(r[1]), "=r"(r[2]), "=r"(r[3]) : "r"(addr));
}
__device__ __forceinline__ void mma_f16(float &d0, float &d1, float &d2, float &d3,
                                        const unsigned* a, unsigned b0, unsigned b1) {
    asm volatile("mma.sync.aligned.m16n8k16.row.col.f32.f16.f16.f32 "
                 "{%0,%1,%2,%3},{%4,%5,%6,%7},{%8,%9},{%0,%1,%2,%3};"
                 : "+f"(d0), "+f"(d1), "+f"(d2), "+f"(d3)
                 : "r"(a[0]), "r"(a[1]), "r"(a[2]), "r"(a[3]), "r"(b0), "r"(b1));
}

// ---------------- kernel 1: prefix sums ----------------
__global__ void prep_kernel(const int* __restrict__ npc) {
    __shared__ int vals[S];
    int t = threadIdx.x;
    vals[t] = npc[t];
    __syncthreads();
    if (t == 0) {
        int a = 0;
        for (int s = 0; s < S; s++) { g_pref[s] = a; a += vals[s]; }
        g_pref[S] = a;
    }
}

// ---------------- kernel 1b: W2 local half -> folded fp16 fragment-major (hi only) ----------------
__global__ void wfrag2_kernel(const float* __restrict__ w2,
                              const float* __restrict__ gm2, const float* __restrict__ va2) {
    int id = blockIdx.x * 256 + threadIdx.x;
    if (id >= 2*4*16*32) return;
    int lane = id & 31;
    int nt = (id >> 5) & 15;
    int ks = (id >> 9) & 3;
    int ch = id >> 11;
    int n = nt * 8 + (lane >> 2);
    int k0 = ch * 64 + ks * 16 + 2 * (lane & 3);
    float s = gm2[n] * rsqrtf(va2[n] + EPS);
    g_w2fh[id] = make_uint2(pack2h(w2[n * 384 + k0] * s,     w2[n * 384 + k0 + 1] * s),
                            pack2h(w2[n * 384 + k0 + 8] * s, w2[n * 384 + k0 + 9] * s));
}

// ---------------- kernel 1c: W3 -> folded fp16 fragment-major (hi only) ----------------
__global__ void wfrag3_kernel(const float* __restrict__ w3, const float* __restrict__ cb3,
                              const float* __restrict__ gm3, const float* __restrict__ bt3,
                              const float* __restrict__ mu3, const float* __restrict__ va3) {
    int id = blockIdx.x * 256 + threadIdx.x;
    if (id >= 8*8*32) return;
    int lane = id & 31;
    int nt = (id >> 5) & 7;
    int ks = id >> 8;
    int n = nt * 8 + (lane >> 2);
    int k0 = ks * 16 + 2 * (lane & 3);
    float s = gm3[n] * rsqrtf(va3[n] + EPS);
    if (ks == 0 && (lane & 3) == 0)
        g_bi3[n] = (cb3[n] - mu3[n]) * s + bt3[n];
    g_w3fh[id] = make_uint2(pack2h(w3[n * 128 + k0] * s,     w3[n * 128 + k0 + 1] * s),
                            pack2h(w3[n * 128 + k0 + 8] * s, w3[n * 128 + k0 + 9] * s));
}

// ---------------- kernel 1d: W_comb = W2g_fold @ ow, b_comb = W2g_fold@ob + bi2f ----------------
// grid 32 x 256: block handles 4 output rows c
__global__ void wcomb_kernel(const float* __restrict__ ow, const float* __restrict__ ob,
                             const float* __restrict__ w2, const float* __restrict__ cb2,
                             const float* __restrict__ gm2, const float* __restrict__ bt2,
                             const float* __restrict__ mu2, const float* __restrict__ va2) {
    __shared__ float wrow[4][256];
    __shared__ float bp[4][256];
    const int t = threadIdx.x;
    const int c0 = blockIdx.x * 4;
#pragma unroll
    for (int r = 0; r < 4; r++) {
        int c = c0 + r;
        float s = gm2[c] * rsqrtf(va2[c] + EPS);
        wrow[r][t] = w2[c * 384 + 128 + t] * s;
    }
    __syncthreads();
    float acc[4] = {0.f, 0.f, 0.f, 0.f};
    for (int ep = 0; ep < 256; ep++) {
        float o = ow[ep * 256 + t];
#pragma unroll
        for (int r = 0; r < 4; r++) acc[r] += wrow[r][ep] * o;
    }
#pragma unroll
    for (int r = 0; r < 4; r++) {
        g_wcomb[(c0 + r) * 256 + t] = acc[r];
        bp[r][t] = wrow[r][t] * ob[t];
    }
    __syncthreads();
    if (t < 4) {
        int c = c0 + t;
        float s = gm2[c] * rsqrtf(va2[c] + EPS);
        float bb = (cb2[c] - mu2[c]) * s + bt2[c];
        float sum = 0.f;
        for (int i = 0; i < 256; i++) sum += bp[t][i];
        g_bcomb[c] = sum + bb;
    }
}

// ---------------- kernel 2: x = gl^T + pos(centroids), grid (64,B) x 256, 4 s/block ----------------
__global__ void xk_kernel(const float* __restrict__ gl, const float* __restrict__ cent,
                          const float* __restrict__ fc1w, const float* __restrict__ fc1b,
                          const float* __restrict__ fc2w, const float* __restrict__ fc2b) {
    const int b = blockIdx.y, s0 = blockIdx.x * 4, e = threadIdx.x;
    float w2r[16];
#pragma unroll
    for (int j = 0; j < 16; j++) w2r[j] = fc2w[e * 16 + j];
    const float fb = fc2b[e];
#pragma unroll
    for (int sr = 0; sr < 4; sr++) {
        int s = s0 + sr;
        float c0 = cent[(b * S + s) * 2 + 0];
        float c1 = cent[(b * S + s) * 2 + 1];
        float pos = fb;
#pragma unroll
        for (int j = 0; j < 16; j++) {
            float hh = fc1b[j] + c0 * fc1w[2 * j] + c1 * fc1w[2 * j + 1];
            hh = (hh >= 0.f) ? hh : 0.01f * hh;
            pos += hh * w2r[j];
        }
        g_x[(b * S + s) * E + e] = gl[(s * B + b) * E + e] + pos;
    }
}

// ---------------- kernel 3: qkv ----------------
__global__ void xqkv_kernel(const float* __restrict__ inw, const float* __restrict__ inb) {
    extern __shared__ float sh[];
    float* xs = sh;
    float* ws = sh + 8320;
    const int t = threadIdx.x;
    const int chunk = blockIdx.x, stile = blockIdx.y, b = blockIdx.z;
    const int s0 = stile * 32;
    for (int p = 0; p < 8; p++) {
        int i4 = t + p * 256;
        int s = i4 >> 6, e4 = i4 & 63;
        *(float4*)&xs[s * 260 + 4 * e4] = *(const float4*)&g_x[(b * S + s0 + s) * E + 4 * e4];
    }
    for (int p = 0; p < 16; p++) {
        int i4 = t + p * 256;
        int o = i4 >> 6, k4 = i4 & 63;
        *(float4*)&ws[o * 268 + 4 * k4] = *(const float4*)&inw[(chunk * 64 + o) * 256 + 4 * k4];
    }
    __syncthreads();
    const int ol = t & 63, sb = (t >> 6) * 8;
    float acc[8];
#pragma unroll
    for (int i = 0; i < 8; i++) acc[i] = 0.f;
#pragma unroll 8
    for (int k4 = 0; k4 < 64; k4++) {
        float4 wv = *(float4*)&ws[ol * 268 + 4 * k4];
#pragma unroll
        for (int i = 0; i < 8; i++) {
            float4 av = *(float4*)&xs[(sb + i) * 260 + 4 * k4];
            acc[i] += wv.x * av.x + wv.y * av.y + wv.z * av.z + wv.w * av.w;
        }
    }
    const int og = chunk * 64 + ol;
    const float bb = inb[og];
    const int part = og >> 8, e = og & 255, hh = e >> 5, d = e & 31;
    float* dst = (part == 0) ? g_q : ((part == 1) ? g_k : g_v);
#pragma unroll
    for (int i = 0; i < 8; i++) {
        int s = s0 + sb + i;
        dst[((b * H + hh) * S + s) * DH + d] = acc[i] + bb;
    }
}

// ---------------- kernel 4: attention, 8-way j-split, grid (8,H,B) x 256 ----------------
__global__ void attn_kernel() {
    extern __shared__ float sh[];
    float* ks  = sh;                 // 8192
    float* vs  = sh + 8192;          // 8192
    float* pm  = vs + 8192;          // 256
    float* pl  = pm + 256;           // 256
    float* pac = pl + 256;           // 256*33
    const int t = threadIdx.x;
    const int b = blockIdx.z, h = blockIdx.y;
    const int base = ((b * H + h) * S) * DH;
    for (int i = t; i < 2048; i += 256) {
        ((float4*)ks)[i] = ((const float4*)(g_k + base))[i];
        ((float4*)vs)[i] = ((const float4*)(g_v + base))[i];
    }
    __syncthreads();
    const int q = t & 31, jh = t >> 5;
    const int qg = blockIdx.x * 32 + q;
    float qr[DH];
#pragma unroll
    for (int i = 0; i < 8; i++) ((float4*)qr)[i] = ((const float4*)(g_q + base + qg * DH))[i];
    const float scale = 0.17677669529663687f;
    float m = -1e30f, l = 0.f, acc[DH];
#pragma unroll
    for (int d = 0; d < DH; d++) acc[d] = 0.f;
    for (int j = jh * 32; j < jh * 32 + 32; j++) {
        float sc = 0.f;
#pragma unroll
        for (int d = 0; d < DH; d++) sc += qr[d] * ks[j * DH + d];
        sc *= scale;
        float mn = fmaxf(m, sc);
        float corr = __expf(m - mn);
        float p = __expf(sc - mn);
        m = mn;
        l = l * corr + p;
#pragma unroll
        for (int d = 0; d < DH; d++) acc[d] = acc[d] * corr + p * vs[j * DH + d];
    }
    pm[t] = m;
    pl[t] = l;
#pragma unroll
    for (int d = 0; d < DH; d++) pac[t * 33 + d] = acc[d];
    __syncthreads();
    if (t < 32) {
        float M = pm[t];
#pragma unroll
        for (int i = 1; i < 8; i++) M = fmaxf(M, pm[i * 32 + t]);
        float L = 0.f, vacc[DH];
#pragma unroll
        for (int d = 0; d < DH; d++) vacc[d] = 0.f;
#pragma unroll
        for (int i = 0; i < 8; i++) {
            float e = __expf(pm[i * 32 + t] - M);
            L += pl[i * 32 + t] * e;
#pragma unroll
            for (int d = 0; d < DH; d++) vacc[d] += pac[(i * 32 + t) * 33 + d] * e;
        }
        float inv = 1.f / L;
        int qo = blockIdx.x * 32 + t;
#pragma unroll
        for (int d = 0; d < DH; d++)
            g_ctx[(b * S + qo) * E + h * DH + d] = vacc[d] * inv;
    }
}

// ---------------- kernel 5: gpb = ctx @ W_comb^T + b_comb, grid (4,8,B) x 256 ----------------
__global__ void gproj_kernel() {
    extern __shared__ float sh[];
    float* cs = sh;          // 32*260
    float* ws = sh + 8320;   // 32*268
    const int t = threadIdx.x;
    const int chunk = blockIdx.x, stile = blockIdx.y, b = blockIdx.z;
    const int s0 = stile * 32;
    for (int p = 0; p < 8; p++) {
        int i4 = t + p * 256;
        int s = i4 >> 6, e4 = i4 & 63;
        *(float4*)&cs[s * 260 + 4 * e4] = *(const float4*)&g_ctx[(b * S + s0 + s) * E + 4 * e4];
    }
    for (int p = 0; p < 8; p++) {
        int i4 = t + p * 256;
        int o = i4 >> 6, k4 = i4 & 63;
        *(float4*)&ws[o * 268 + 4 * k4] = *(const float4*)&g_wcomb[(chunk * 32 + o) * 256 + 4 * k4];
    }
    __syncthreads();
    const int ol = t & 31, sb = (t >> 5) * 4;
    float acc[4] = {0.f, 0.f, 0.f, 0.f};
#pragma unroll 8
    for (int k4 = 0; k4 < 64; k4++) {
        float4 wv = *(float4*)&ws[ol * 268 + 4 * k4];
#pragma unroll
        for (int i = 0; i < 4; i++) {
            float4 av = *(float4*)&cs[(sb + i) * 260 + 4 * k4];
            acc[i] += wv.x * av.x + wv.y * av.y + wv.z * av.z + wv.w * av.w;
        }
    }
    const int og = chunk * 32 + ol;
    const float bb = g_bcomb[og];
#pragma unroll
    for (int i = 0; i < 4; i++)
        g_gpb[(b * S + s0 + sb + i) * 128 + og] = acc[i] + bb;
}

// ---------------- kernel 6: fp16 mma.sync point-MLP (hi-only W, gpb init) ----------------
#define AB(i)   ((i) ? 18432 : 0)
#define MT_H3   0                     // overlay: 128*67*4 = 34304 <= 36864
#define MT_BI3  36864                 // 256
#define MT_W4S  37120                 // 512
#define MT_PREF 37632                 // 1028
#define MT_CID  38660                 // 512
#define MT_SIZE 39424

__global__ __launch_bounds__(256)
void mlp_mma_kernel(const float* __restrict__ lo, const float* __restrict__ w4,
                    const float* __restrict__ b4, float* __restrict__ out) {
    extern __shared__ __align__(16) char smc[];
    float* h3f  = (float*)(smc + MT_H3);
    float* bi3s = (float*)(smc + MT_BI3);
    float* w4s  = (float*)(smc + MT_W4S);
    int*   pref = (int*)(smc + MT_PREF);
    int*   cid  = (int*)(smc + MT_CID);
    const unsigned smemB = (unsigned)__cvta_generic_to_shared(smc);

    const int t = threadIdx.x;
    const int w = t >> 5, lane = t & 31;
    const int b = blockIdx.y;
    const int n0 = blockIdx.x * 128;

    if (t < 128) w4s[t] = w4[t];
    if (t >= 128 && t < 192) bi3s[t - 128] = g_bi3[t - 128];
    if (t < 256) pref[t] = g_pref[t];
    __syncthreads();
    if (t < 128) {
        int i = n0 + t;
        int s = 0;
#pragma unroll
        for (int step = 128; step >= 1; step >>= 1)
            if (s + step <= 255 && pref[s + step] <= i) s += step;
        cid[t] = s;
    }
    __syncthreads();

    const int grow = t >> 1, gkh = (t & 1) * 32;
    const int arow = (lane & 7) + ((lane >> 3) & 1) * 8;
    const int akb  = (lane >> 4) * 16;
    const int wm = w >> 2, wn = w & 3;
    const int g = lane >> 2, tg = lane & 3;

    // ---- gather chunk 0 (lo k 0-63) ----
    {
        const float* src = lo + ((size_t)(b * NN + n0 + grow)) * LD + gkh;
        unsigned hb = smemB + AB(0) + grow * 144 + gkh * 2;
#pragma unroll
        for (int j = 0; j < 8; j++) {
            float4 v = *(const float4*)(src + 4 * j);
            sts64(hb + 8 * j, pack2h(v.x, v.y), pack2h(v.z, v.w));
        }
    }

    // ---- init accumulators from gpb[cid] (fp32-exact global half) ----
    float acc[4][4][4];
#pragma unroll
    for (int mt = 0; mt < 4; mt++) {
        int r0 = wm * 64 + mt * 16 + g;
        const float* g0 = g_gpb + ((size_t)(b * S + cid[r0])) * 128;
        const float* g1 = g_gpb + ((size_t)(b * S + cid[r0 + 8])) * 128;
#pragma unroll
        for (int nt = 0; nt < 4; nt++) {
            int col = wn * 32 + nt * 8 + 2 * tg;
            float2 v0 = *(const float2*)(g0 + col);
            float2 v1 = *(const float2*)(g1 + col);
            acc[mt][nt][0] = v0.x; acc[mt][nt][1] = v0.y;
            acc[mt][nt][2] = v1.x; acc[mt][nt][3] = v1.y;
        }
    }
    __syncthreads();

    // ---- stage 1: 2 chunks of K=64 (lo only), hi-only ----
    for (int c = 0; c < 2; c++) {
        float4 nxt[8];
        if (c == 0) {
            const float* src = lo + ((size_t)(b * NN + n0 + grow)) * LD + 64 + gkh;
#pragma unroll
            for (int j = 0; j < 8; j++) nxt[j] = *(const float4*)(src + 4 * j);
        }
        const unsigned ah = smemB + AB(c);
#pragma unroll
        for (int ks = 0; ks < 4; ks++) {
            uint2 bh[4];
#pragma unroll
            for (int nt = 0; nt < 4; nt++) {
                int idx = ((c * 4 + ks) * 16 + wn * 4 + nt) * 32 + lane;
                bh[nt] = __ldg(&g_w2fh[idx]);
            }
#pragma unroll
            for (int mt = 0; mt < 4; mt++) {
                unsigned base = (wm * 64 + mt * 16 + arow) * 144 + ks * 32 + akb;
                unsigned fah[4];
                ldmx4(fah, ah + base);
#pragma unroll
                for (int nt = 0; nt < 4; nt++)
                    mma_f16(acc[mt][nt][0], acc[mt][nt][1], acc[mt][nt][2], acc[mt][nt][3],
                            fah, bh[nt].x, bh[nt].y);
            }
        }
        if (c == 0) {
            unsigned hb = smemB + AB(1) + grow * 144 + gkh * 2;
#pragma unroll
            for (int j = 0; j < 8; j++)
                sts64(hb + 8 * j, pack2h(nxt[j].x, nxt[j].y), pack2h(nxt[j].z, nxt[j].w));
        }
        __syncthreads();
    }

    // ---- stage1 epilogue: relu -> fp16 h2 into A buffers ----
    {
#pragma unroll
        for (int mt = 0; mt < 4; mt++) {
#pragma unroll
            for (int nt = 0; nt < 4; nt++) {
                int col = wn * 32 + nt * 8 + 2 * tg;
                int bufi = col >> 6;
                unsigned off = (col & 63) * 2;
                int r0 = wm * 64 + mt * 16 + g;
                *(unsigned*)(smc + AB(bufi) + r0 * 144 + off) =
                    pack2h(fmaxf(acc[mt][nt][0], 0.f), fmaxf(acc[mt][nt][1], 0.f));
                int r1 = r0 + 8;
                *(unsigned*)(smc + AB(bufi) + r1 * 144 + off) =
                    pack2h(fmaxf(acc[mt][nt][2], 0.f), fmaxf(acc[mt][nt][3], 0.f));
            }
        }
    }
    __syncthreads();

    // ---- stage 2: K=128 (8 ksteps), warp tile 32 pts x 32 ch, hi-only ----
    const int wm2 = w >> 1, wn2 = w & 1;
    float ac2[2][4][4];
#pragma unroll
    for (int mt = 0; mt < 2; mt++)
#pragma unroll
        for (int nt = 0; nt < 4; nt++)
#pragma unroll
            for (int r = 0; r < 4; r++) ac2[mt][nt][r] = 0.f;

#pragma unroll
    for (int ks = 0; ks < 8; ks++) {
        const unsigned ah = smemB + AB(ks >> 2);
        const int ki = ks & 3;
        uint2 bh[4];
#pragma unroll
        for (int nt = 0; nt < 4; nt++) {
            int idx = (ks * 8 + wn2 * 4 + nt) * 32 + lane;
            bh[nt] = __ldg(&g_w3fh[idx]);
        }
#pragma unroll
        for (int mt = 0; mt < 2; mt++) {
            unsigned base = (wm2 * 32 + mt * 16 + arow) * 144 + ki * 32 + akb;
            unsigned fah[4];
            ldmx4(fah, ah + base);
#pragma unroll
            for (int nt = 0; nt < 4; nt++)
                mma_f16(ac2[mt][nt][0], ac2[mt][nt][1], ac2[mt][nt][2], ac2[mt][nt][3],
                        fah, bh[nt].x, bh[nt].y);
        }
    }
    __syncthreads();

    // ---- stage2 epilogue: h3 fp32 overlay ----
    {
#pragma unroll
        for (int mt = 0; mt < 2; mt++) {
#pragma unroll
            for (int nt = 0; nt < 4; nt++) {
                int col = wn2 * 32 + nt * 8 + 2 * tg;
                float bia = bi3s[col], bib = bi3s[col + 1];
                int r0 = wm2 * 32 + mt * 16 + g;
                h3f[r0 * 67 + col]     = fmaxf(ac2[mt][nt][0] + bia, 0.f);
                h3f[r0 * 67 + col + 1] = fmaxf(ac2[mt][nt][1] + bib, 0.f);
                int r1 = r0 + 8;
                h3f[r1 * 67 + col]     = fmaxf(ac2[mt][nt][2] + bia, 0.f);
                h3f[r1 * 67 + col + 1] = fmaxf(ac2[mt][nt][3] + bib, 0.f);
            }
        }
    }
    __syncthreads();

    // ---- conv4 + transposed write ----
    if (t < 128) {
        const int p = t;
        float a0 = b4[0], a1 = b4[1];
#pragma unroll
        for (int k = 0; k < 64; k++) {
            float v = h3f[p * 67 + k];
            a0 += v * w4s[k];
            a1 += v * w4s[64 + k];
        }
        out[(size_t)(b * NC + 0) * NN + n0 + p] = a0;
        out[(size_t)(b * NC + 1) * NN + n0 + p] = a1;
    }
}

// ---------------- launch ----------------
extern "C" void kernel_launch(void* const* d_in, const int* in_sizes, int n_in,
                              void* d_out, int out_size) {
    const float* gl   = (const float*)d_in[0];
    const float* lo   = (const float*)d_in[1];
    const float* cent = (const float*)d_in[2];
    const int*   npc  = (const int*)  d_in[3];
    const float* fc1w = (const float*)d_in[4];
    const float* fc1b = (const float*)d_in[5];
    const float* fc2w = (const float*)d_in[6];
    const float* fc2b = (const float*)d_in[7];
    const float* inw  = (const float*)d_in[8];
    const float* inb  = (const float*)d_in[9];
    const float* ow   = (const float*)d_in[10];
    const float* ob   = (const float*)d_in[11];
    const float* w2   = (const float*)d_in[12];
    const float* cb2  = (const float*)d_in[13];
    const float* gm2  = (const float*)d_in[14];
    const float* bt2  = (const float*)d_in[15];
    const float* mu2  = (const float*)d_in[16];
    const float* va2  = (const float*)d_in[17];
    const float* w3   = (const float*)d_in[18];
    const float* cb3  = (const float*)d_in[19];
    const float* gm3  = (const float*)d_in[20];
    const float* bt3  = (const float*)d_in[21];
    const float* mu3  = (const float*)d_in[22];
    const float* va3  = (const float*)d_in[23];
    const float* w4   = (const float*)d_in[24];
    const float* b4   = (const float*)d_in[25];
    float* out = (float*)d_out;

    const int xqkv_smem = (8320 + 17152) * 4;
    const int attn_smem = (8192 * 2 + 256 * 2 + 8448) * 4;
    const int gp_smem   = (8320 + 8576) * 4;

    cudaFuncSetAttribute(xqkv_kernel,    cudaFuncAttributeMaxDynamicSharedMemorySize, xqkv_smem);
    cudaFuncSetAttribute(attn_kernel,    cudaFuncAttributeMaxDynamicSharedMemorySize, attn_smem);
    cudaFuncSetAttribute(gproj_kernel,   cudaFuncAttributeMaxDynamicSharedMemorySize, gp_smem);
    cudaFuncSetAttribute(mlp_mma_kernel, cudaFuncAttributeMaxDynamicSharedMemorySize, MT_SIZE);

    prep_kernel<<<1, 256>>>(npc);
    wfrag2_kernel<<<16, 256>>>(w2, gm2, va2);
    wfrag3_kernel<<<8, 256>>>(w3, cb3, gm3, bt3, mu3, va3);
    wcomb_kernel<<<32, 256>>>(ow, ob, w2, cb2, gm2, bt2, mu2, va2);
    xk_kernel<<<dim3(64, B), 256>>>(gl, cent, fc1w, fc1b, fc2w, fc2b);
    xqkv_kernel<<<dim3(12, 8, B), 256, xqkv_smem>>>(inw, inb);
    attn_kernel<<<dim3(8, H, B), 256, attn_smem>>>();
    gproj_kernel<<<dim3(4, 8, B), 256, gp_smem>>>();
    mlp_mma_kernel<<<dim3(NN / 128, B), 256, MT_SIZE>>>(lo, w4, b4, out);
}

// round 12
// speedup vs baseline: 9.9510x; 1.1321x over previous
#include <cuda_runtime.h>
#include <cuda_fp16.h>
#include <math.h>

#define B 4
#define S 256
#define E 256
#define H 8
#define DH 32
#define LD 128
#define NN 65536
#define NC 2
#define EPS 1e-5f

// ---------------- scratch ----------------
__device__ __align__(16) float g_q[B*H*S*DH];
__device__ __align__(16) float g_k[B*H*S*DH];
__device__ __align__(16) float g_v[B*H*S*DH];
__device__ __align__(16) float g_ctx[B*S*E];
__device__ __align__(16) float g_x[B*S*E];
__device__ __align__(16) float g_gpb[B*S*128];     // per-cluster global-half of h2 pre-activation
__device__ __align__(16) float g_wpart[4*128*256]; // wcomb K-split partials
__device__ __align__(16) float g_wcomb[128*256];   // W2g_fold @ ow
__device__ float g_bcomb[128];
__device__ int g_pref[S + 1];
// W2 local half folded fp16 (hi only), fragment-major: [chunk2][kstep4][ntile16][lane32] uint2
__device__ __align__(16) uint2 g_w2fh[2*4*16*32];
// W3 folded fp16 (hi only), fragment-major: [kstep8][ntile8][lane32]
__device__ __align__(16) uint2 g_w3fh[8*8*32];
__device__ float g_bi3[64];

// ---------------- helpers ----------------
__device__ __forceinline__ unsigned pack2h(float a0, float a1) {
    __half2 h = __floats2half2_rn(a0, a1);
    return *reinterpret_cast<unsigned*>(&h);
}
__device__ __forceinline__ void sts64(unsigned a, unsigned x, unsigned y) {
    asm volatile("st.shared.v2.b32 [%0],{%1,%2};" :: "r"(a), "r"(x), "r"(y) : "memory");
}
__device__ __forceinline__ void ldmx4(unsigned* r, unsigned addr) {
    asm volatile("ldmatrix.sync.aligned.m8n8.x4.shared.b16 {%0,%1,%2,%3},[%4];"
                 : "=r"(r[0]), "=r"(r[1]), "=r"(r[2]), "=r"(r[3]) : "r"(addr));
}
__device__ __forceinline__ void mma_f16(float &d0, float &d1, float &d2, float &d3,
                                        const unsigned* a, unsigned b0, unsigned b1) {
    asm volatile("mma.sync.aligned.m16n8k16.row.col.f32.f16.f16.f32 "
                 "{%0,%1,%2,%3},{%4,%5,%6,%7},{%8,%9},{%0,%1,%2,%3};"
                 : "+f"(d0), "+f"(d1), "+f"(d2), "+f"(d3)
                 : "r"(a[0]), "r"(a[1]), "r"(a[2]), "r"(a[3]), "r"(b0), "r"(b1));
}

// ---------------- kernel 1: prefix sums ----------------
__global__ void prep_kernel(const int* __restrict__ npc) {
    __shared__ int vals[S];
    int t = threadIdx.x;
    vals[t] = npc[t];
    __syncthreads();
    if (t == 0) {
        int a = 0;
        for (int s = 0; s < S; s++) { g_pref[s] = a; a += vals[s]; }
        g_pref[S] = a;
    }
}

// ---------------- kernel 1b: W2 local half -> folded fp16 fragment-major (hi only) ----------------
__global__ void wfrag2_kernel(const float* __restrict__ w2,
                              const float* __restrict__ gm2, const float* __restrict__ va2) {
    int id = blockIdx.x * 256 + threadIdx.x;
    if (id >= 2*4*16*32) return;
    int lane = id & 31;
    int nt = (id >> 5) & 15;
    int ks = (id >> 9) & 3;
    int ch = id >> 11;
    int n = nt * 8 + (lane >> 2);
    int k0 = ch * 64 + ks * 16 + 2 * (lane & 3);
    float s = gm2[n] * rsqrtf(va2[n] + EPS);
    g_w2fh[id] = make_uint2(pack2h(w2[n * 384 + k0] * s,     w2[n * 384 + k0 + 1] * s),
                            pack2h(w2[n * 384 + k0 + 8] * s, w2[n * 384 + k0 + 9] * s));
}

// ---------------- kernel 1c: W3 -> folded fp16 fragment-major (hi only) ----------------
__global__ void wfrag3_kernel(const float* __restrict__ w3, const float* __restrict__ cb3,
                              const float* __restrict__ gm3, const float* __restrict__ bt3,
                              const float* __restrict__ mu3, const float* __restrict__ va3) {
    int id = blockIdx.x * 256 + threadIdx.x;
    if (id >= 8*8*32) return;
    int lane = id & 31;
    int nt = (id >> 5) & 7;
    int ks = id >> 8;
    int n = nt * 8 + (lane >> 2);
    int k0 = ks * 16 + 2 * (lane & 3);
    float s = gm3[n] * rsqrtf(va3[n] + EPS);
    if (ks == 0 && (lane & 3) == 0)
        g_bi3[n] = (cb3[n] - mu3[n]) * s + bt3[n];
    g_w3fh[id] = make_uint2(pack2h(w3[n * 128 + k0] * s,     w3[n * 128 + k0 + 1] * s),
                            pack2h(w3[n * 128 + k0 + 8] * s, w3[n * 128 + k0 + 9] * s));
}

// ---------------- kernel 1d-a: wcomb partials, grid (4 ksplit, 128 rows) x 256 ----------------
__global__ void wcomb_part_kernel(const float* __restrict__ ow, const float* __restrict__ w2,
                                  const float* __restrict__ gm2, const float* __restrict__ va2) {
    __shared__ float wrow[64];
    const int t = threadIdx.x;
    const int ks = blockIdx.x, c = blockIdx.y;
    if (t < 64) {
        float s = gm2[c] * rsqrtf(va2[c] + EPS);
        wrow[t] = w2[c * 384 + 128 + ks * 64 + t] * s;
    }
    __syncthreads();
    float acc = 0.f;
#pragma unroll 8
    for (int ep = 0; ep < 64; ep++)
        acc += wrow[ep] * __ldg(&ow[(ks * 64 + ep) * 256 + t]);
    g_wpart[(ks * 128 + c) * 256 + t] = acc;
}

// ---------------- kernel 1d-b: wcomb reduce + b_comb, grid 128 x 256 ----------------
__global__ void wcomb_reduce_kernel(const float* __restrict__ ob, const float* __restrict__ w2,
                                    const float* __restrict__ cb2, const float* __restrict__ gm2,
                                    const float* __restrict__ bt2, const float* __restrict__ mu2,
                                    const float* __restrict__ va2) {
    __shared__ float red[256];
    const int t = threadIdx.x, c = blockIdx.x;
    g_wcomb[c * 256 + t] = g_wpart[c * 256 + t] + g_wpart[(128 + c) * 256 + t] +
                           g_wpart[(256 + c) * 256 + t] + g_wpart[(384 + c) * 256 + t];
    float s = gm2[c] * rsqrtf(va2[c] + EPS);
    red[t] = w2[c * 384 + 128 + t] * s * ob[t];
    __syncthreads();
    for (int st = 128; st >= 1; st >>= 1) {
        if (t < st) red[t] += red[t + st];
        __syncthreads();
    }
    if (t == 0)
        g_bcomb[c] = red[0] + (cb2[c] - mu2[c]) * s + bt2[c];
}

// ---------------- kernel 2: x = gl^T + pos(centroids), grid (64,B) x 256, 4 s/block ----------------
__global__ void xk_kernel(const float* __restrict__ gl, const float* __restrict__ cent,
                          const float* __restrict__ fc1w, const float* __restrict__ fc1b,
                          const float* __restrict__ fc2w, const float* __restrict__ fc2b) {
    const int b = blockIdx.y, s0 = blockIdx.x * 4, e = threadIdx.x;
    float w2r[16];
#pragma unroll
    for (int j = 0; j < 16; j++) w2r[j] = fc2w[e * 16 + j];
    const float fb = fc2b[e];
#pragma unroll
    for (int sr = 0; sr < 4; sr++) {
        int s = s0 + sr;
        float c0 = cent[(b * S + s) * 2 + 0];
        float c1 = cent[(b * S + s) * 2 + 1];
        float pos = fb;
#pragma unroll
        for (int j = 0; j < 16; j++) {
            float hh = fc1b[j] + c0 * fc1w[2 * j] + c1 * fc1w[2 * j + 1];
            hh = (hh >= 0.f) ? hh : 0.01f * hh;
            pos += hh * w2r[j];
        }
        g_x[(b * S + s) * E + e] = gl[(s * B + b) * E + e] + pos;
    }
}

// ---------------- kernel 3: qkv ----------------
__global__ void xqkv_kernel(const float* __restrict__ inw, const float* __restrict__ inb) {
    extern __shared__ float sh[];
    float* xs = sh;
    float* ws = sh + 8320;
    const int t = threadIdx.x;
    const int chunk = blockIdx.x, stile = blockIdx.y, b = blockIdx.z;
    const int s0 = stile * 32;
    for (int p = 0; p < 8; p++) {
        int i4 = t + p * 256;
        int s = i4 >> 6, e4 = i4 & 63;
        *(float4*)&xs[s * 260 + 4 * e4] = *(const float4*)&g_x[(b * S + s0 + s) * E + 4 * e4];
    }
    for (int p = 0; p < 16; p++) {
        int i4 = t + p * 256;
        int o = i4 >> 6, k4 = i4 & 63;
        *(float4*)&ws[o * 268 + 4 * k4] = *(const float4*)&inw[(chunk * 64 + o) * 256 + 4 * k4];
    }
    __syncthreads();
    const int ol = t & 63, sb = (t >> 6) * 8;
    float acc[8];
#pragma unroll
    for (int i = 0; i < 8; i++) acc[i] = 0.f;
#pragma unroll 8
    for (int k4 = 0; k4 < 64; k4++) {
        float4 wv = *(float4*)&ws[ol * 268 + 4 * k4];
#pragma unroll
        for (int i = 0; i < 8; i++) {
            float4 av = *(float4*)&xs[(sb + i) * 260 + 4 * k4];
            acc[i] += wv.x * av.x + wv.y * av.y + wv.z * av.z + wv.w * av.w;
        }
    }
    const int og = chunk * 64 + ol;
    const float bb = inb[og];
    const int part = og >> 8, e = og & 255, hh = e >> 5, d = e & 31;
    float* dst = (part == 0) ? g_q : ((part == 1) ? g_k : g_v);
#pragma unroll
    for (int i = 0; i < 8; i++) {
        int s = s0 + sb + i;
        dst[((b * H + hh) * S + s) * DH + d] = acc[i] + bb;
    }
}

// ---------------- kernel 4: attention, 8-way j-split, grid (8,H,B) x 256 ----------------
__global__ void attn_kernel() {
    extern __shared__ float sh[];
    float* ks  = sh;                 // 8192
    float* vs  = sh + 8192;          // 8192
    float* pm  = vs + 8192;          // 256
    float* pl  = pm + 256;           // 256
    float* pac = pl + 256;           // 256*33
    const int t = threadIdx.x;
    const int b = blockIdx.z, h = blockIdx.y;
    const int base = ((b * H + h) * S) * DH;
    for (int i = t; i < 2048; i += 256) {
        ((float4*)ks)[i] = ((const float4*)(g_k + base))[i];
        ((float4*)vs)[i] = ((const float4*)(g_v + base))[i];
    }
    __syncthreads();
    const int q = t & 31, jh = t >> 5;
    const int qg = blockIdx.x * 32 + q;
    float qr[DH];
#pragma unroll
    for (int i = 0; i < 8; i++) ((float4*)qr)[i] = ((const float4*)(g_q + base + qg * DH))[i];
    const float scale = 0.17677669529663687f;
    float m = -1e30f, l = 0.f, acc[DH];
#pragma unroll
    for (int d = 0; d < DH; d++) acc[d] = 0.f;
    for (int j = jh * 32; j < jh * 32 + 32; j++) {
        float sc = 0.f;
#pragma unroll
        for (int d = 0; d < DH; d++) sc += qr[d] * ks[j * DH + d];
        sc *= scale;
        float mn = fmaxf(m, sc);
        float corr = __expf(m - mn);
        float p = __expf(sc - mn);
        m = mn;
        l = l * corr + p;
#pragma unroll
        for (int d = 0; d < DH; d++) acc[d] = acc[d] * corr + p * vs[j * DH + d];
    }
    pm[t] = m;
    pl[t] = l;
#pragma unroll
    for (int d = 0; d < DH; d++) pac[t * 33 + d] = acc[d];
    __syncthreads();
    if (t < 32) {
        float M = pm[t];
#pragma unroll
        for (int i = 1; i < 8; i++) M = fmaxf(M, pm[i * 32 + t]);
        float L = 0.f, vacc[DH];
#pragma unroll
        for (int d = 0; d < DH; d++) vacc[d] = 0.f;
#pragma unroll
        for (int i = 0; i < 8; i++) {
            float e = __expf(pm[i * 32 + t] - M);
            L += pl[i * 32 + t] * e;
#pragma unroll
            for (int d = 0; d < DH; d++) vacc[d] += pac[(i * 32 + t) * 33 + d] * e;
        }
        float inv = 1.f / L;
        int qo = blockIdx.x * 32 + t;
#pragma unroll
        for (int d = 0; d < DH; d++)
            g_ctx[(b * S + qo) * E + h * DH + d] = vacc[d] * inv;
    }
}

// ---------------- kernel 5: gpb = ctx @ W_comb^T + b_comb, grid (4,8,B) x 256 ----------------
__global__ void gproj_kernel() {
    extern __shared__ float sh[];
    float* cs = sh;          // 32*260
    float* ws = sh + 8320;   // 32*268
    const int t = threadIdx.x;
    const int chunk = blockIdx.x, stile = blockIdx.y, b = blockIdx.z;
    const int s0 = stile * 32;
    for (int p = 0; p < 8; p++) {
        int i4 = t + p * 256;
        int s = i4 >> 6, e4 = i4 & 63;
        *(float4*)&cs[s * 260 + 4 * e4] = *(const float4*)&g_ctx[(b * S + s0 + s) * E + 4 * e4];
    }
    for (int p = 0; p < 8; p++) {
        int i4 = t + p * 256;
        int o = i4 >> 6, k4 = i4 & 63;
        *(float4*)&ws[o * 268 + 4 * k4] = *(const float4*)&g_wcomb[(chunk * 32 + o) * 256 + 4 * k4];
    }
    __syncthreads();
    const int ol = t & 31, sb = (t >> 5) * 4;
    float acc[4] = {0.f, 0.f, 0.f, 0.f};
#pragma unroll 8
    for (int k4 = 0; k4 < 64; k4++) {
        float4 wv = *(float4*)&ws[ol * 268 + 4 * k4];
#pragma unroll
        for (int i = 0; i < 4; i++) {
            float4 av = *(float4*)&cs[(sb + i) * 260 + 4 * k4];
            acc[i] += wv.x * av.x + wv.y * av.y + wv.z * av.z + wv.w * av.w;
        }
    }
    const int og = chunk * 32 + ol;
    const float bb = g_bcomb[og];
#pragma unroll
    for (int i = 0; i < 4; i++)
        g_gpb[(b * S + s0 + sb + i) * 128 + og] = acc[i] + bb;
}

// ---------------- kernel 6: fp16 mma.sync point-MLP (hi-only W, gpb init) ----------------
#define AB(i)   ((i) ? 18432 : 0)
#define MT_H3   0                     // overlay: 128*67*4 = 34304 <= 36864
#define MT_BI3  36864                 // 256
#define MT_W4S  37120                 // 512
#define MT_PREF 37632                 // 1028
#define MT_CID  38660                 // 512
#define MT_SIZE 39424

__global__ __launch_bounds__(256)
void mlp_mma_kernel(const float* __restrict__ lo, const float* __restrict__ w4,
                    const float* __restrict__ b4, float* __restrict__ out) {
    extern __shared__ __align__(16) char smc[];
    float* h3f  = (float*)(smc + MT_H3);
    float* bi3s = (float*)(smc + MT_BI3);
    float* w4s  = (float*)(smc + MT_W4S);
    int*   pref = (int*)(smc + MT_PREF);
    int*   cid  = (int*)(smc + MT_CID);
    const unsigned smemB = (unsigned)__cvta_generic_to_shared(smc);

    const int t = threadIdx.x;
    const int w = t >> 5, lane = t & 31;
    const int b = blockIdx.y;
    const int n0 = blockIdx.x * 128;

    if (t < 128) w4s[t] = w4[t];
    if (t >= 128 && t < 192) bi3s[t - 128] = g_bi3[t - 128];
    if (t < 256) pref[t] = g_pref[t];
    __syncthreads();
    if (t < 128) {
        int i = n0 + t;
        int s = 0;
#pragma unroll
        for (int step = 128; step >= 1; step >>= 1)
            if (s + step <= 255 && pref[s + step] <= i) s += step;
        cid[t] = s;
    }
    __syncthreads();

    const int grow = t >> 1, gkh = (t & 1) * 32;
    const int arow = (lane & 7) + ((lane >> 3) & 1) * 8;
    const int akb  = (lane >> 4) * 16;
    const int wm = w >> 2, wn = w & 3;
    const int g = lane >> 2, tg = lane & 3;

    // ---- gather chunk 0 (lo k 0-63) ----
    {
        const float* src = lo + ((size_t)(b * NN + n0 + grow)) * LD + gkh;
        unsigned hb = smemB + AB(0) + grow * 144 + gkh * 2;
#pragma unroll
        for (int j = 0; j < 8; j++) {
            float4 v = *(const float4*)(src + 4 * j);
            sts64(hb + 8 * j, pack2h(v.x, v.y), pack2h(v.z, v.w));
        }
    }

    // ---- init accumulators from gpb[cid] (fp32-exact global half) ----
    float acc[4][4][4];
#pragma unroll
    for (int mt = 0; mt < 4; mt++) {
        int r0 = wm * 64 + mt * 16 + g;
        const float* g0 = g_gpb + ((size_t)(b * S + cid[r0])) * 128;
        const float* g1 = g_gpb + ((size_t)(b * S + cid[r0 + 8])) * 128;
#pragma unroll
        for (int nt = 0; nt < 4; nt++) {
            int col = wn * 32 + nt * 8 + 2 * tg;
            float2 v0 = *(const float2*)(g0 + col);
            float2 v1 = *(const float2*)(g1 + col);
            acc[mt][nt][0] = v0.x; acc[mt][nt][1] = v0.y;
            acc[mt][nt][2] = v1.x; acc[mt][nt][3] = v1.y;
        }
    }
    __syncthreads();

    // ---- stage 1: 2 chunks of K=64 (lo only), hi-only ----
    for (int c = 0; c < 2; c++) {
        float4 nxt[8];
        if (c == 0) {
            const float* src = lo + ((size_t)(b * NN + n0 + grow)) * LD + 64 + gkh;
#pragma unroll
            for (int j = 0; j < 8; j++) nxt[j] = *(const float4*)(src + 4 * j);
        }
        const unsigned ah = smemB + AB(c);
#pragma unroll
        for (int ks = 0; ks < 4; ks++) {
            uint2 bh[4];
#pragma unroll
            for (int nt = 0; nt < 4; nt++) {
                int idx = ((c * 4 + ks) * 16 + wn * 4 + nt) * 32 + lane;
                bh[nt] = __ldg(&g_w2fh[idx]);
            }
#pragma unroll
            for (int mt = 0; mt < 4; mt++) {
                unsigned base = (wm * 64 + mt * 16 + arow) * 144 + ks * 32 + akb;
                unsigned fah[4];
                ldmx4(fah, ah + base);
#pragma unroll
                for (int nt = 0; nt < 4; nt++)
                    mma_f16(acc[mt][nt][0], acc[mt][nt][1], acc[mt][nt][2], acc[mt][nt][3],
                            fah, bh[nt].x, bh[nt].y);
            }
        }
        if (c == 0) {
            unsigned hb = smemB + AB(1) + grow * 144 + gkh * 2;
#pragma unroll
            for (int j = 0; j < 8; j++)
                sts64(hb + 8 * j, pack2h(nxt[j].x, nxt[j].y), pack2h(nxt[j].z, nxt[j].w));
        }
        __syncthreads();
    }

    // ---- stage1 epilogue: relu -> fp16 h2 into A buffers ----
    {
#pragma unroll
        for (int mt = 0; mt < 4; mt++) {
#pragma unroll
            for (int nt = 0; nt < 4; nt++) {
                int col = wn * 32 + nt * 8 + 2 * tg;
                int bufi = col >> 6;
                unsigned off = (col & 63) * 2;
                int r0 = wm * 64 + mt * 16 + g;
                *(unsigned*)(smc + AB(bufi) + r0 * 144 + off) =
                    pack2h(fmaxf(acc[mt][nt][0], 0.f), fmaxf(acc[mt][nt][1], 0.f));
                int r1 = r0 + 8;
                *(unsigned*)(smc + AB(bufi) + r1 * 144 + off) =
                    pack2h(fmaxf(acc[mt][nt][2], 0.f), fmaxf(acc[mt][nt][3], 0.f));
            }
        }
    }
    __syncthreads();

    // ---- stage 2: K=128 (8 ksteps), warp tile 32 pts x 32 ch, hi-only ----
    const int wm2 = w >> 1, wn2 = w & 1;
    float ac2[2][4][4];
#pragma unroll
    for (int mt = 0; mt < 2; mt++)
#pragma unroll
        for (int nt = 0; nt < 4; nt++)
#pragma unroll
            for (int r = 0; r < 4; r++) ac2[mt][nt][r] = 0.f;

#pragma unroll
    for (int ks = 0; ks < 8; ks++) {
        const unsigned ah = smemB + AB(ks >> 2);
        const int ki = ks & 3;
        uint2 bh[4];
#pragma unroll
        for (int nt = 0; nt < 4; nt++) {
            int idx = (ks * 8 + wn2 * 4 + nt) * 32 + lane;
            bh[nt] = __ldg(&g_w3fh[idx]);
        }
#pragma unroll
        for (int mt = 0; mt < 2; mt++) {
            unsigned base = (wm2 * 32 + mt * 16 + arow) * 144 + ki * 32 + akb;
            unsigned fah[4];
            ldmx4(fah, ah + base);
#pragma unroll
            for (int nt = 0; nt < 4; nt++)
                mma_f16(ac2[mt][nt][0], ac2[mt][nt][1], ac2[mt][nt][2], ac2[mt][nt][3],
                        fah, bh[nt].x, bh[nt].y);
        }
    }
    __syncthreads();

    // ---- stage2 epilogue: h3 fp32 overlay ----
    {
#pragma unroll
        for (int mt = 0; mt < 2; mt++) {
#pragma unroll
            for (int nt = 0; nt < 4; nt++) {
                int col = wn2 * 32 + nt * 8 + 2 * tg;
                float bia = bi3s[col], bib = bi3s[col + 1];
                int r0 = wm2 * 32 + mt * 16 + g;
                h3f[r0 * 67 + col]     = fmaxf(ac2[mt][nt][0] + bia, 0.f);
                h3f[r0 * 67 + col + 1] = fmaxf(ac2[mt][nt][1] + bib, 0.f);
                int r1 = r0 + 8;
                h3f[r1 * 67 + col]     = fmaxf(ac2[mt][nt][2] + bia, 0.f);
                h3f[r1 * 67 + col + 1] = fmaxf(ac2[mt][nt][3] + bib, 0.f);
            }
        }
    }
    __syncthreads();

    // ---- conv4 + transposed write ----
    if (t < 128) {
        const int p = t;
        float a0 = b4[0], a1 = b4[1];
#pragma unroll
        for (int k = 0; k < 64; k++) {
            float v = h3f[p * 67 + k];
            a0 += v * w4s[k];
            a1 += v * w4s[64 + k];
        }
        out[(size_t)(b * NC + 0) * NN + n0 + p] = a0;
        out[(size_t)(b * NC + 1) * NN + n0 + p] = a1;
    }
}

// ---------------- launch ----------------
extern "C" void kernel_launch(void* const* d_in, const int* in_sizes, int n_in,
                              void* d_out, int out_size) {
    const float* gl   = (const float*)d_in[0];
    const float* lo   = (const float*)d_in[1];
    const float* cent = (const float*)d_in[2];
    const int*   npc  = (const int*)  d_in[3];
    const float* fc1w = (const float*)d_in[4];
    const float* fc1b = (const float*)d_in[5];
    const float* fc2w = (const float*)d_in[6];
    const float* fc2b = (const float*)d_in[7];
    const float* inw  = (const float*)d_in[8];
    const float* inb  = (const float*)d_in[9];
    const float* ow   = (const float*)d_in[10];
    const float* ob   = (const float*)d_in[11];
    const float* w2   = (const float*)d_in[12];
    const float* cb2  = (const float*)d_in[13];
    const float* gm2  = (const float*)d_in[14];
    const float* bt2  = (const float*)d_in[15];
    const float* mu2  = (const float*)d_in[16];
    const float* va2  = (const float*)d_in[17];
    const float* w3   = (const float*)d_in[18];
    const float* cb3  = (const float*)d_in[19];
    const float* gm3  = (const float*)d_in[20];
    const float* bt3  = (const float*)d_in[21];
    const float* mu3  = (const float*)d_in[22];
    const float* va3  = (const float*)d_in[23];
    const float* w4   = (const float*)d_in[24];
    const float* b4   = (const float*)d_in[25];
    float* out = (float*)d_out;

    const int xqkv_smem = (8320 + 17152) * 4;
    const int attn_smem = (8192 * 2 + 256 * 2 + 8448) * 4;
    const int gp_smem   = (8320 + 8576) * 4;

    cudaFuncSetAttribute(xqkv_kernel,    cudaFuncAttributeMaxDynamicSharedMemorySize, xqkv_smem);
    cudaFuncSetAttribute(attn_kernel,    cudaFuncAttributeMaxDynamicSharedMemorySize, attn_smem);
    cudaFuncSetAttribute(gproj_kernel,   cudaFuncAttributeMaxDynamicSharedMemorySize, gp_smem);
    cudaFuncSetAttribute(mlp_mma_kernel, cudaFuncAttributeMaxDynamicSharedMemorySize, MT_SIZE);

    prep_kernel<<<1, 256>>>(npc);
    wfrag2_kernel<<<16, 256>>>(w2, gm2, va2);
    wfrag3_kernel<<<8, 256>>>(w3, cb3, gm3, bt3, mu3, va3);
    wcomb_part_kernel<<<dim3(4, 128), 256>>>(ow, w2, gm2, va2);
    wcomb_reduce_kernel<<<128, 256>>>(ob, w2, cb2, gm2, bt2, mu2, va2);
    xk_kernel<<<dim3(64, B), 256>>>(gl, cent, fc1w, fc1b, fc2w, fc2b);
    xqkv_kernel<<<dim3(12, 8, B), 256, xqkv_smem>>>(inw, inb);
    attn_kernel<<<dim3(8, H, B), 256, attn_smem>>>();
    gproj_kernel<<<dim3(4, 8, B), 256, gp_smem>>>();
    mlp_mma_kernel<<<dim3(NN / 128, B), 256, MT_SIZE>>>(lo, w4, b4, out);
}